// round 12
// baseline (speedup 1.0000x reference)
#include <cuda_runtime.h>
#include <cuda_bf16.h>
#include <math.h>
#include <stdint.h>

#define BB 256
#define LL 128
#define CC 256
#define HH 512
#define G4H 2048   // 4*HH

// ---------------- scratch (device globals: no allocation allowed) ----------------
__device__ float g_preG2[(size_t)BB * LL * G4H];  // 32768 x 2048, cols interleaved h*4+g
__device__ float g_W2[HH * G4H];                  // Wmh @ Whm (orig col layout)
__device__ float g_Wcomb[CC * G4H];               // Wih + Wmx@Whm (orig col layout)
__device__ float g_biasc[G4H];                    // combined bias row (orig layout)
__device__ volatile unsigned g_barg[256];         // per-b-tile lo/hi half counters
__device__ alignas(256) __nv_bfloat16 g_A2[(size_t)BB * LL * 768];  // [Xhi|Xhi|Xlo]
__device__ alignas(256) __nv_bfloat16 g_B2[(size_t)G4H * 768];      // [n_il][Whi;Wlo;Whi]
__device__ alignas(256) __nv_bfloat16 g_W2Thi[(size_t)G4H * HH];    // [n_il][k] hi
__device__ alignas(256) __nv_bfloat16 g_W2Tlo[(size_t)G4H * HH];    // [n_il][k] lo
__device__ alignas(256) __nv_bfloat16 g_hhi[BB * HH];               // h bf16 hi [b][k]
__device__ alignas(256) __nv_bfloat16 g_hlo[BB * HH];               // h bf16 lo [b][k]

typedef unsigned long long ull;

// ---------------- helpers ---------------------------------------------------------
__device__ __forceinline__ ull pk2(float x, float y) {
    ull r; asm("mov.b64 %0, {%1, %2};" : "=l"(r) : "f"(x), "f"(y)); return r;
}
__device__ __forceinline__ void upk2(ull v, float& x, float& y) {
    asm("mov.b64 {%0, %1}, %2;" : "=f"(x), "=f"(y) : "l"(v));
}
__device__ __forceinline__ void fma2(ull& d, ull a, ull b) {
    asm("fma.rn.f32x2 %0, %1, %2, %0;" : "+l"(d) : "l"(a), "l"(b));
}
__device__ __forceinline__ float tanha(float x) {
    float y; asm("tanh.approx.f32 %0, %1;" : "=f"(y) : "f"(x)); return y;
}
__device__ __forceinline__ float sigma(float x) {
    return fmaf(tanha(x * 0.5f), 0.5f, 0.5f);
}
__device__ __forceinline__ uint32_t smem_u32(const void* p) {
    uint32_t a;
    asm("{ .reg .u64 t; cvta.to.shared.u64 t, %1; cvt.u32.u64 %0, t; }" : "=r"(a) : "l"(p));
    return a;
}
__device__ __forceinline__ void ldm_x4(uint32_t& r0, uint32_t& r1, uint32_t& r2,
                                       uint32_t& r3, uint32_t addr) {
    asm volatile("ldmatrix.sync.aligned.m8n8.x4.shared.b16 {%0,%1,%2,%3}, [%4];"
                 : "=r"(r0), "=r"(r1), "=r"(r2), "=r"(r3) : "r"(addr));
}
__device__ __forceinline__ void mma16816(float* d, const uint32_t* a, uint32_t b0, uint32_t b1) {
    asm volatile("mma.sync.aligned.m16n8k16.row.col.f32.bf16.bf16.f32 "
                 "{%0,%1,%2,%3}, {%4,%5,%6,%7}, {%8,%9}, {%0,%1,%2,%3};"
                 : "+f"(d[0]), "+f"(d[1]), "+f"(d[2]), "+f"(d[3])
                 : "r"(a[0]), "r"(a[1]), "r"(a[2]), "r"(a[3]), "r"(b0), "r"(b1));
}
__device__ __forceinline__ void cpasync16(uint32_t dst, const void* src) {
    asm volatile("cp.async.cg.shared.global [%0], [%1], 16;" :: "r"(dst), "l"(src) : "memory");
}
#define CP_COMMIT() asm volatile("cp.async.commit_group;" ::: "memory")
#define CP_WAIT2()  asm volatile("cp.async.wait_group 2;" ::: "memory")
#define CP_WAIT1()  asm volatile("cp.async.wait_group 1;" ::: "memory")
#define CP_WAIT0()  asm volatile("cp.async.wait_group 0;" ::: "memory")

// ---------------- init ------------------------------------------------------------
__global__ void zero_init() {
    int i = threadIdx.x;
    if (i < 8) g_barg[i * 32] = 0u;   // lo: bt*64, hi: bt*64+32
}

// ---------------- attention: softmax is time-invariant ---------------------------
__global__ void attn_xtilde(const float* __restrict__ x, const float* __restrict__ Wa,
                            const float* __restrict__ ba, float* __restrict__ out_xt) {
    int b = blockIdx.x;
    int c = threadIdx.x;
    __shared__ float wx[LL];
    __shared__ float red[CC];
    if (c < LL) wx[c] = Wa[2 * HH + c];
    __syncthreads();

    const float* xb = x + (size_t)b * LL * CC;
    float s = 0.f;
#pragma unroll 4
    for (int l = 0; l < LL; l++) s += xb[l * CC + c] * wx[l];
    s += ba[0];

    red[c] = s; __syncthreads();
#pragma unroll
    for (int st = 128; st > 0; st >>= 1) {
        if (c < st) red[c] = fmaxf(red[c], red[c + st]);
        __syncthreads();
    }
    float m = red[0];
    __syncthreads();
    float e = expf(s - m);
    red[c] = e; __syncthreads();
#pragma unroll
    for (int st = 128; st > 0; st >>= 1) {
        if (c < st) red[c] += red[c + st];
        __syncthreads();
    }
    float alpha = e / red[0];

    float* ob = out_xt + (size_t)b * LL * CC;
#pragma unroll 4
    for (int l = 0; l < LL; l++) ob[l * CC + c] = alpha * xb[l * CC + c];
}

// ---------------- combined bias row: bih + bhm + (bmx+bmh)@Whm --------------------
__global__ void bias_comb(const float* __restrict__ bih, const float* __restrict__ bhm,
                          const float* __restrict__ bmx, const float* __restrict__ bmh,
                          const float* __restrict__ Whm) {
    __shared__ float bm[HH];
    int tid = threadIdx.x;
    for (int i = tid; i < HH; i += 256) bm[i] = bmx[i] + bmh[i];
    __syncthreads();
    int j = blockIdx.x * 256 + tid;
    float s = bih[j] + bhm[j];
#pragma unroll 8
    for (int k = 0; k < HH; k++) s += bm[k] * Whm[(size_t)k * G4H + j];
    g_biasc[j] = s;
}

// ---------------- stacked weight SGEMM: [Wmx;Wmh] @ Whm -> {Wcomb, W2} -----------
#define BM2 64
#define BN 128
#define BK 16

__global__ __launch_bounds__(256, 2) void sgemm_w(
    const float* __restrict__ Wmx, const float* __restrict__ Wmh,
    const float* __restrict__ Whm, const float* __restrict__ Wih,
    float* __restrict__ Wcomb, float* __restrict__ W2) {
    __shared__ alignas(16) float As[BK][BM2 + 4];
    __shared__ alignas(16) float Bs[BK][BN];

    int tid = threadIdx.x;
    int bm = blockIdx.y * BM2;
    int bn = blockIdx.x * BN;
    int tx = tid & 15, ty = tid >> 4;
    int row = ty * 4, col = tx * 8;

    const int lr = tid >> 2;
    const int lq = (tid & 3) << 2;
    int r_glob = bm + lr;
    const float* Asrc = (r_glob < CC) ? (Wmx + (size_t)r_glob * HH)
                                      : (Wmh + (size_t)(r_glob - CC) * HH);

    ull acc[4][4];
#pragma unroll
    for (int i = 0; i < 4; i++)
#pragma unroll
        for (int j = 0; j < 4; j++) acc[i][j] = 0ULL;

    for (int k0 = 0; k0 < HH; k0 += BK) {
        {
            float4 v = *(const float4*)(Asrc + k0 + lq);
            As[lq + 0][lr] = v.x; As[lq + 1][lr] = v.y;
            As[lq + 2][lr] = v.z; As[lq + 3][lr] = v.w;
        }
#pragma unroll
        for (int i = 0; i < 2; i++) {
            int idx = tid + i * 256;
            int r = idx >> 5;
            int c = (idx & 31) << 2;
            *(float4*)&Bs[r][c] = *(const float4*)(Whm + (size_t)(k0 + r) * G4H + bn + c);
        }
        __syncthreads();
#pragma unroll
        for (int kk = 0; kk < BK; kk++) {
            float4 a0 = *(const float4*)&As[kk][row];
            float4 b0 = *(const float4*)&Bs[kk][col];
            float4 b1 = *(const float4*)&Bs[kk][col + 4];
            ull bp0 = pk2(b0.x, b0.y), bp1 = pk2(b0.z, b0.w);
            ull bp2 = pk2(b1.x, b1.y), bp3 = pk2(b1.z, b1.w);
            float av[4] = {a0.x, a0.y, a0.z, a0.w};
#pragma unroll
            for (int i = 0; i < 4; i++) {
                ull ap = pk2(av[i], av[i]);
                fma2(acc[i][0], ap, bp0);
                fma2(acc[i][1], ap, bp1);
                fma2(acc[i][2], ap, bp2);
                fma2(acc[i][3], ap, bp3);
            }
        }
        __syncthreads();
    }

#pragma unroll
    for (int i = 0; i < 4; i++) {
        int rg = bm + row + i;
        float o[8];
#pragma unroll
        for (int j = 0; j < 4; j++) upk2(acc[i][j], o[2 * j], o[2 * j + 1]);
        float* outp;
        if (rg < CC) {
            size_t off = (size_t)rg * G4H + bn + col;
            float4 c0 = *(const float4*)(Wih + off);
            float4 c1 = *(const float4*)(Wih + off + 4);
            o[0] += c0.x; o[1] += c0.y; o[2] += c0.z; o[3] += c0.w;
            o[4] += c1.x; o[5] += c1.y; o[6] += c1.z; o[7] += c1.w;
            outp = Wcomb + off;
        } else {
            outp = W2 + (size_t)(rg - CC) * G4H + bn + col;
        }
        *(float4*)(outp) = make_float4(o[0], o[1], o[2], o[3]);
        *(float4*)(outp + 4) = make_float4(o[4], o[5], o[6], o[7]);
    }
}

// ---------------- bf16 split conversions ------------------------------------------
__device__ __forceinline__ uint32_t pkbf2(float a, float b) {
    __nv_bfloat162 h2 = __floats2bfloat162_rn(a, b);
    return *(uint32_t*)&h2;
}

// x [32768 x 256] fp32 -> A2 [32768 x 768] bf16 (cols: [hi | hi | lo])
__global__ void conv_x(const float* __restrict__ x) {
    int i = blockIdx.x * blockDim.x + threadIdx.x;
    int m = i >> 6;
    int c = (i & 63) << 2;
    float4 v = *(const float4*)(x + (size_t)m * CC + c);
    float h0 = __bfloat162float(__float2bfloat16(v.x));
    float h1 = __bfloat162float(__float2bfloat16(v.y));
    float h2 = __bfloat162float(__float2bfloat16(v.z));
    float h3 = __bfloat162float(__float2bfloat16(v.w));
    uint2 hi = make_uint2(pkbf2(v.x, v.y), pkbf2(v.z, v.w));
    uint2 lo = make_uint2(pkbf2(v.x - h0, v.y - h1), pkbf2(v.z - h2, v.w - h3));
    __nv_bfloat16* row = g_A2 + (size_t)m * 768;
    *(uint2*)(row + c) = hi;
    *(uint2*)(row + 256 + c) = hi;
    *(uint2*)(row + 512 + c) = lo;
}

// Wcomb [256 x 2048 orig] -> B2 [2048 interleaved-n x 768] bf16 (k: [hi | lo | hi])
__global__ void conv_w() {
    int i = blockIdx.x * blockDim.x + threadIdx.x;
    int n = i >> 6;                       // interleaved col: n = h*4+g
    int k4 = (i & 63) << 2;
    int corig = (n & 3) * HH + (n >> 2);  // original col: g*HH+h
    float v0 = g_Wcomb[(size_t)(k4 + 0) * G4H + corig];
    float v1 = g_Wcomb[(size_t)(k4 + 1) * G4H + corig];
    float v2 = g_Wcomb[(size_t)(k4 + 2) * G4H + corig];
    float v3 = g_Wcomb[(size_t)(k4 + 3) * G4H + corig];
    float h0 = __bfloat162float(__float2bfloat16(v0));
    float h1 = __bfloat162float(__float2bfloat16(v1));
    float h2 = __bfloat162float(__float2bfloat16(v2));
    float h3 = __bfloat162float(__float2bfloat16(v3));
    uint2 hi = make_uint2(pkbf2(v0, v1), pkbf2(v2, v3));
    uint2 lo = make_uint2(pkbf2(v0 - h0, v1 - h1), pkbf2(v2 - h2, v3 - h3));
    __nv_bfloat16* row = g_B2 + (size_t)n * 768;
    *(uint2*)(row + k4) = hi;
    *(uint2*)(row + 256 + k4) = lo;
    *(uint2*)(row + 512 + k4) = hi;
}

// W2 [512 k x 2048 orig] -> W2T hi/lo [2048 interleaved-n x 512 k] bf16
__global__ void conv_w2t() {
    int i = blockIdx.x * blockDim.x + threadIdx.x;  // (n, k-group of 4)
    int n = i >> 7;                                 // 512/4 = 128 groups
    int k4 = (i & 127) << 2;
    int corig = (n & 3) * HH + (n >> 2);
    float v0 = g_W2[(size_t)(k4 + 0) * G4H + corig];
    float v1 = g_W2[(size_t)(k4 + 1) * G4H + corig];
    float v2 = g_W2[(size_t)(k4 + 2) * G4H + corig];
    float v3 = g_W2[(size_t)(k4 + 3) * G4H + corig];
    float h0 = __bfloat162float(__float2bfloat16(v0));
    float h1 = __bfloat162float(__float2bfloat16(v1));
    float h2 = __bfloat162float(__float2bfloat16(v2));
    float h3 = __bfloat162float(__float2bfloat16(v3));
    *(uint2*)(g_W2Thi + (size_t)n * HH + k4) = make_uint2(pkbf2(v0, v1), pkbf2(v2, v3));
    *(uint2*)(g_W2Tlo + (size_t)n * HH + k4) =
        make_uint2(pkbf2(v0 - h0, v1 - h1), pkbf2(v2 - h2, v3 - h3));
}

// ---------------- HMMA GEMM: preG2 = A2 @ B2^T (3-buffer, 1 sync/chunk) ----------
#define GSM_BUF 32768   // A 16KB + B 16KB per buffer

__global__ __launch_bounds__(256) void gemm_mma(float* __restrict__ Cm) {
    extern __shared__ char sm[];
    uint32_t sb = smem_u32(sm);
    const int tid = threadIdx.x;
    const int wid = tid >> 5, lane = tid & 31;
    const int bn = blockIdx.x * 128, bm = blockIdx.y * 128;
    const int wm0 = (wid & 1) * 64, wn0 = (wid >> 1) * 32;

    float C[4][4][4];
#pragma unroll
    for (int mi = 0; mi < 4; mi++)
#pragma unroll
        for (int ni = 0; ni < 4; ni++)
#pragma unroll
            for (int e = 0; e < 4; e++) C[mi][ni][e] = 0.f;

    const int lr = tid >> 3;
    const int lk8 = tid & 7;
#define ISSUE(kc) do { \
        int _buf = (kc) % 3; \
        uint32_t _Ab = sb + _buf * GSM_BUF; \
        uint32_t _Bb = _Ab + 16384; \
        _Pragma("unroll") \
        for (int _it = 0; _it < 4; _it++) { \
            int _r = lr + _it * 32; \
            uint32_t _sw = (uint32_t)(_r * 128 + ((lk8 ^ (_r & 7)) << 4)); \
            cpasync16(_Ab + _sw, g_A2 + (size_t)(bm + _r) * 768 + (kc) * 64 + lk8 * 8); \
            cpasync16(_Bb + _sw, g_B2 + (size_t)(bn + _r) * 768 + (kc) * 64 + lk8 * 8); \
        } \
        CP_COMMIT(); \
    } while (0)

    ISSUE(0);
    ISSUE(1);

    const int lmid = lane >> 3;
    const int lrow8 = lane & 7;

    for (int kc = 0; kc < 12; kc++) {
        if (kc < 11) { CP_WAIT1(); } else { CP_WAIT0(); }
        __syncthreads();
        if (kc + 2 < 12) ISSUE(kc + 2);   // buffer (kc+2)%3=(kc-1)%3, safe past sync
        uint32_t Ab = sb + (kc % 3) * GSM_BUF;
        uint32_t Bb = Ab + 16384;
#pragma unroll
        for (int ks = 0; ks < 4; ks++) {
            uint32_t a[4][4], b[2][4];
#pragma unroll
            for (int mi = 0; mi < 4; mi++) {
                int row = wm0 + mi * 16 + ((lmid & 1) << 3) + lrow8;
                int k8 = ks * 2 + (lmid >> 1);
                ldm_x4(a[mi][0], a[mi][1], a[mi][2], a[mi][3],
                       Ab + row * 128 + ((k8 ^ (row & 7)) << 4));
            }
#pragma unroll
            for (int nb = 0; nb < 2; nb++) {
                int row = wn0 + nb * 16 + ((lmid >> 1) << 3) + lrow8;
                int k8 = ks * 2 + (lmid & 1);
                ldm_x4(b[nb][0], b[nb][1], b[nb][2], b[nb][3],
                       Bb + row * 128 + ((k8 ^ (row & 7)) << 4));
            }
#pragma unroll
            for (int mi = 0; mi < 4; mi++)
#pragma unroll
                for (int ni = 0; ni < 4; ni++)
                    mma16816(C[mi][ni], a[mi],
                             b[ni >> 1][(ni & 1) * 2], b[ni >> 1][(ni & 1) * 2 + 1]);
        }
    }

    const int qid = lane >> 2, tq = lane & 3;
#pragma unroll
    for (int ni = 0; ni < 4; ni++) {
        int col = bn + wn0 + ni * 8 + tq * 2;
#pragma unroll
        for (int mi = 0; mi < 4; mi++) {
            int row = bm + wm0 + mi * 16 + qid;
            *(float2*)(Cm + (size_t)row * G4H + col) = make_float2(C[mi][ni][0], C[mi][ni][1]);
            *(float2*)(Cm + (size_t)(row + 8) * G4H + col) = make_float2(C[mi][ni][2], C[mi][ni][3]);
        }
    }
#undef ISSUE
}

// ---------------- HMMA persistent recurrence (half-split barriers) ----------------
// 128 CTAs: x = n-tile (64 interleaved gate cols = 16 h), y = b-tile (64 rows).
// W2T hi/lo 128KB in SMEM; 4 slots x 32KB A, 3-deep. Barrier split lo/hi per b-tile:
// slot 0/2 consume h k[0,256) from nt<16; slot 1/3 consume k[256,512) from nt>=16.
#define LSM_BLO 65536
#define LSM_A   131072
#define LSM_TOT (131072 + 3 * 32768)   // 229376 bytes

__global__ __launch_bounds__(256, 1) void lstm_mma(
    const float* __restrict__ preG2, float* __restrict__ out_h, float* __restrict__ out_c) {
    extern __shared__ char sm[];
    uint32_t sb = smem_u32(sm);
    const int tid = threadIdx.x;
    const int wid = tid >> 5, lane = tid & 31;
    const int nt = blockIdx.x, bt = blockIdx.y;
    const int b0 = bt * 64;
    const int n0 = nt * 64;
    const int wm = (wid & 1) * 32, wn = (wid >> 1) * 16;
    const int lmid = lane >> 3, lrow8 = lane & 7;
    const int qid = lane >> 2, tq = lane & 3;
    const int parity = tq & 1;
    const int lr = tid >> 3, lk8 = tid & 7;
    const int my_half = (nt < 16) ? 0 : 32;   // arrival counter offset

    // load W2T slices (hi/lo) into SMEM once: 64 n-rows x 512 k, swizzled
    for (int i = tid; i < 4096; i += 256) {
        int r = i >> 6, c = i & 63;
        uint32_t dst = (uint32_t)(r * 1024 + (((c & 56) | ((c ^ r) & 7)) << 4));
        *(uint4*)(sm + dst) = *(const uint4*)(g_W2Thi + (size_t)(n0 + r) * HH + c * 8);
        *(uint4*)(sm + LSM_BLO + dst) = *(const uint4*)(g_W2Tlo + (size_t)(n0 + r) * HH + c * 8);
    }

    int bb[2], hh[2];
#pragma unroll
    for (int mi = 0; mi < 2; mi++) bb[mi] = b0 + wm + mi * 16 + qid + parity * 8;
#pragma unroll
    for (int ni = 0; ni < 2; ni++) hh[ni] = nt * 16 + (wid >> 1) * 4 + ni * 2 + (tq >> 1);

    float bgv[2][4];
#pragma unroll
    for (int ni = 0; ni < 2; ni++)
#pragma unroll
        for (int g = 0; g < 4; g++) bgv[ni][g] = g_biasc[g * HH + hh[ni]];

    float Creg[2][2] = {{0.f, 0.f}, {0.f, 0.f}};
    __syncthreads();

    // slot s (0..3): s<2 -> Ahi (dual B terms), s>=2 -> Alo (Bhi only).
    // slot = 32KB = 4 sub-chunks of 64 rows x 64 k. buffer = s % 3 (3-deep).
#define AISSUE3(s) do { \
        uint32_t _ab = sb + LSM_A + ((s) % 3) * 32768; \
        const __nv_bfloat16* _src = ((s) < 2) ? g_hhi : g_hlo; \
        int _kb = ((s) & 1) * 256; \
        _Pragma("unroll") \
        for (int _it = 0; _it < 8; _it++) { \
            int _half = _it >> 1; \
            int _r = lr + (_it & 1) * 32; \
            cpasync16(_ab + _half * 8192 + (uint32_t)(_r * 128 + ((lk8 ^ (_r & 7)) << 4)), \
                      _src + (size_t)(b0 + _r) * HH + _kb + _half * 64 + lk8 * 8); \
        } \
        CP_COMMIT(); \
    } while (0)

    // prefetch preG2 gate vectors for t=0
    float4 pv[2][2];
#pragma unroll
    for (int mi = 0; mi < 2; mi++)
#pragma unroll
        for (int ni = 0; ni < 2; ni++)
            pv[mi][ni] = __ldg((const float4*)(preG2 + ((size_t)bb[mi] * LL + 0) * G4H + hh[ni] * 4));

    for (int t = 0; t < LL; t++) {
        float C[2][2][4];
#pragma unroll
        for (int mi = 0; mi < 2; mi++)
#pragma unroll
            for (int ni = 0; ni < 2; ni++)
#pragma unroll
                for (int e = 0; e < 4; e++) C[mi][ni][e] = 0.f;

        if (t > 0) {
            unsigned tgt = 16u * (unsigned)t;
            // wait lo half (producers of k[0,256)) then issue slot 0
            if (tid == 0) { while (g_barg[bt * 64] < tgt) { __nanosleep(32); } }
            __syncthreads();
            AISSUE3(0);
            // wait hi half (producers of k[256,512)) then issue slots 1,2
            if (tid == 0) { while (g_barg[bt * 64 + 32] < tgt) { __nanosleep(32); } }
            __syncthreads();
            AISSUE3(1);
            AISSUE3(2);
            for (int s = 0; s < 4; s++) {
                if (s == 0) { CP_WAIT2(); } else if (s < 3) { CP_WAIT1(); } else { CP_WAIT0(); }
                __syncthreads();
                if (s == 1) AISSUE3(3);
                uint32_t Ab = sb + LSM_A + (s % 3) * 32768;
                bool dual = (s < 2);
#pragma unroll
                for (int half = 0; half < 4; half++) {
                    uint32_t Abh = Ab + half * 8192;
                    int kc = (s & 1) * 4 + half;   // 0..7
#pragma unroll
                    for (int ks = 0; ks < 4; ks++) {
                        uint32_t a[2][4];
#pragma unroll
                        for (int mi = 0; mi < 2; mi++) {
                            int row = wm + mi * 16 + ((lmid & 1) << 3) + lrow8;
                            int k8 = ks * 2 + (lmid >> 1);
                            ldm_x4(a[mi][0], a[mi][1], a[mi][2], a[mi][3],
                                   Abh + row * 128 + ((k8 ^ (row & 7)) << 4));
                        }
                        int brow = wn + ((lmid >> 1) << 3) + lrow8;
                        int k8b = kc * 8 + ks * 2 + (lmid & 1);
                        uint32_t boff = (uint32_t)(brow * 1024 +
                            (((k8b & 56) | ((k8b ^ brow) & 7)) << 4));
                        uint32_t bh[4];
                        ldm_x4(bh[0], bh[1], bh[2], bh[3], sb + boff);
#pragma unroll
                        for (int mi = 0; mi < 2; mi++)
#pragma unroll
                            for (int ni = 0; ni < 2; ni++)
                                mma16816(C[mi][ni], a[mi], bh[ni * 2], bh[ni * 2 + 1]);
                        if (dual) {
                            uint32_t bl[4];
                            ldm_x4(bl[0], bl[1], bl[2], bl[3], sb + LSM_BLO + boff);
#pragma unroll
                            for (int mi = 0; mi < 2; mi++)
#pragma unroll
                                for (int ni = 0; ni < 2; ni++)
                                    mma16816(C[mi][ni], a[mi], bl[ni * 2], bl[ni * 2 + 1]);
                        }
                    }
                }
            }
        }

        // epilogue: parity exchange + cell update
#pragma unroll
        for (int mi = 0; mi < 2; mi++) {
#pragma unroll
            for (int ni = 0; ni < 2; ni++) {
                float s0 = parity ? C[mi][ni][0] : C[mi][ni][2];
                float s1 = parity ? C[mi][ni][1] : C[mi][ni][3];
                float r0 = __shfl_xor_sync(0xffffffffu, s0, 1);
                float r1 = __shfl_xor_sync(0xffffffffu, s1, 1);
                float gi, gf, gg, go;
                if (!parity) { gi = C[mi][ni][0]; gf = C[mi][ni][1]; gg = r0; go = r1; }
                else         { gi = r0; gf = r1; gg = C[mi][ni][2]; go = C[mi][ni][3]; }
                gi += pv[mi][ni].x + bgv[ni][0];
                gf += pv[mi][ni].y + bgv[ni][1];
                gg += pv[mi][ni].z + bgv[ni][2];
                go += pv[mi][ni].w + bgv[ni][3];

                float Cn = sigma(gf) * Creg[mi][ni] + sigma(gi) * tanha(gg);
                float hn = sigma(go) * tanha(Cn);
                Creg[mi][ni] = Cn;

                size_t ob = ((size_t)bb[mi] * LL + t) * HH + hh[ni];
                __stcs(out_h + ob, hn);
                __stcs(out_c + ob, Cn);
                __nv_bfloat16 hb = __float2bfloat16(hn);
                g_hhi[bb[mi] * HH + hh[ni]] = hb;
                g_hlo[bb[mi] * HH + hh[ni]] =
                    __float2bfloat16(hn - __bfloat162float(hb));
            }
        }

        // arrival on own half counter; prefetch next step's preG2 first
        if (t != LL - 1) {
#pragma unroll
            for (int mi = 0; mi < 2; mi++)
#pragma unroll
                for (int ni = 0; ni < 2; ni++)
                    pv[mi][ni] = __ldg((const float4*)(preG2 +
                        ((size_t)bb[mi] * LL + (t + 1)) * G4H + hh[ni] * 4));
            __threadfence();
            __syncthreads();
            if (tid == 0) atomicAdd((unsigned*)&g_barg[bt * 64 + my_half], 1u);
        }
    }
#undef AISSUE3
}

// ---------------- launch ----------------
extern "C" void kernel_launch(void* const* d_in, const int* in_sizes, int n_in,
                              void* d_out, int out_size) {
    const float* x   = (const float*)d_in[0];
    const float* Wih = (const float*)d_in[1];
    const float* bih = (const float*)d_in[2];
    const float* Wmx = (const float*)d_in[3];
    const float* bmx = (const float*)d_in[4];
    const float* Wmh = (const float*)d_in[5];
    const float* bmh = (const float*)d_in[6];
    const float* Whm = (const float*)d_in[7];
    const float* bhm = (const float*)d_in[8];
    const float* Wa  = (const float*)d_in[9];
    const float* ba  = (const float*)d_in[10];

    float* out    = (float*)d_out;
    float* out_h  = out;
    float* out_c  = out + (size_t)BB * LL * HH;
    float* out_xt = out + (size_t)2 * BB * LL * HH;

    float *preG2, *W2, *Wcomb;
    cudaGetSymbolAddress((void**)&preG2, g_preG2);
    cudaGetSymbolAddress((void**)&W2, g_W2);
    cudaGetSymbolAddress((void**)&Wcomb, g_Wcomb);

    // (1) stacked weight GEMM: [Wmx;Wmh] @ Whm -> {Wcomb(+Wih), W2}
    sgemm_w<<<dim3(G4H / BN, (CC + HH) / BM2), 256>>>(Wmx, Wmh, Whm, Wih, Wcomb, W2);
    // (2) Wcomb -> B2 (interleaved n, split bf16)
    conv_w<<<(G4H * 64) / 256, 256>>>();
    // (3) X -> A2 (split bf16)
    conv_x<<<(BB * LL * CC / 4) / 256, 256>>>(x);
    // (4) preG2 = A2 @ B2^T  (3-buffer, 1 sync/chunk)
    cudaFuncSetAttribute(gemm_mma, cudaFuncAttributeMaxDynamicSharedMemorySize, 3 * GSM_BUF);
    gemm_mma<<<dim3(G4H / 128, (BB * LL) / 128), 256, 3 * GSM_BUF>>>(preG2);

    // (5) barrier reset
    zero_init<<<1, 32>>>();
    // (6) attention path
    attn_xtilde<<<BB, 256>>>(x, Wa, ba, out_xt);
    // (7) combined bias row (orig layout)
    bias_comb<<<G4H / 256, 256>>>(bih, bhm, bmx, bmh, Whm);
    // (8) W2 -> W2T hi/lo (interleaved n, split bf16)
    conv_w2t<<<(G4H * 128) / 256, 256>>>();

    // (9) persistent HMMA recurrence: half-split barriers
    cudaFuncSetAttribute(lstm_mma, cudaFuncAttributeMaxDynamicSharedMemorySize, LSM_TOT);
    lstm_mma<<<dim3(32, 4), 256, LSM_TOT>>>(preG2, out_h, out_c);
}

// round 13
// speedup vs baseline: 1.1225x; 1.1225x over previous
#include <cuda_runtime.h>
#include <cuda_bf16.h>
#include <math.h>
#include <stdint.h>

#define BB 256
#define LL 128
#define CC 256
#define HH 512
#define G4H 2048   // 4*HH

// ---------------- scratch (device globals: no allocation allowed) ----------------
__device__ float g_preG2[(size_t)BB * LL * G4H];  // 32768 x 2048, cols interleaved h*4+g
__device__ float g_W2[HH * G4H];                  // Wmh @ Whm (orig col layout)
__device__ float g_Wcomb[CC * G4H];               // Wih + Wmx@Whm (orig col layout)
__device__ float g_biasc[G4H];                    // combined bias row (orig layout)
__device__ volatile unsigned g_barg[256];         // 4 group barrier counters (stride 64)
__device__ alignas(256) __nv_bfloat16 g_A2[(size_t)BB * LL * 768];  // [Xhi|Xhi|Xlo]
__device__ alignas(256) __nv_bfloat16 g_B2[(size_t)G4H * 768];      // [n_il][Whi;Wlo;Whi]
__device__ alignas(256) __nv_bfloat16 g_W2Thi[(size_t)G4H * HH];    // [n_il][k] hi
__device__ alignas(256) __nv_bfloat16 g_W2Tlo[(size_t)G4H * HH];    // [n_il][k] lo
__device__ alignas(256) __nv_bfloat16 g_hhi[BB * HH];               // h bf16 hi [b][k]
__device__ alignas(256) __nv_bfloat16 g_hlo[BB * HH];               // h bf16 lo [b][k]

typedef unsigned long long ull;

// ---------------- helpers ---------------------------------------------------------
__device__ __forceinline__ ull pk2(float x, float y) {
    ull r; asm("mov.b64 %0, {%1, %2};" : "=l"(r) : "f"(x), "f"(y)); return r;
}
__device__ __forceinline__ void upk2(ull v, float& x, float& y) {
    asm("mov.b64 {%0, %1}, %2;" : "=f"(x), "=f"(y) : "l"(v));
}
__device__ __forceinline__ void fma2(ull& d, ull a, ull b) {
    asm("fma.rn.f32x2 %0, %1, %2, %0;" : "+l"(d) : "l"(a), "l"(b));
}
__device__ __forceinline__ float tanha(float x) {
    float y; asm("tanh.approx.f32 %0, %1;" : "=f"(y) : "f"(x)); return y;
}
__device__ __forceinline__ float sigma(float x) {
    return fmaf(tanha(x * 0.5f), 0.5f, 0.5f);
}
__device__ __forceinline__ uint32_t smem_u32(const void* p) {
    uint32_t a;
    asm("{ .reg .u64 t; cvta.to.shared.u64 t, %1; cvt.u32.u64 %0, t; }" : "=r"(a) : "l"(p));
    return a;
}
__device__ __forceinline__ void ldm_x4(uint32_t& r0, uint32_t& r1, uint32_t& r2,
                                       uint32_t& r3, uint32_t addr) {
    asm volatile("ldmatrix.sync.aligned.m8n8.x4.shared.b16 {%0,%1,%2,%3}, [%4];"
                 : "=r"(r0), "=r"(r1), "=r"(r2), "=r"(r3) : "r"(addr));
}
__device__ __forceinline__ void mma16816(float* d, const uint32_t* a, uint32_t b0, uint32_t b1) {
    asm volatile("mma.sync.aligned.m16n8k16.row.col.f32.bf16.bf16.f32 "
                 "{%0,%1,%2,%3}, {%4,%5,%6,%7}, {%8,%9}, {%0,%1,%2,%3};"
                 : "+f"(d[0]), "+f"(d[1]), "+f"(d[2]), "+f"(d[3])
                 : "r"(a[0]), "r"(a[1]), "r"(a[2]), "r"(a[3]), "r"(b0), "r"(b1));
}
__device__ __forceinline__ void cpasync16(uint32_t dst, const void* src) {
    asm volatile("cp.async.cg.shared.global [%0], [%1], 16;" :: "r"(dst), "l"(src) : "memory");
}
#define CP_COMMIT() asm volatile("cp.async.commit_group;" ::: "memory")
#define CP_WAIT2()  asm volatile("cp.async.wait_group 2;" ::: "memory")
#define CP_WAIT1()  asm volatile("cp.async.wait_group 1;" ::: "memory")
#define CP_WAIT0()  asm volatile("cp.async.wait_group 0;" ::: "memory")

// ---------------- init ------------------------------------------------------------
__global__ void zero_init() {
    int i = threadIdx.x;
    if (i < 4) g_barg[i * 64] = 0u;
}

// ---------------- attention: softmax is time-invariant ---------------------------
__global__ void attn_xtilde(const float* __restrict__ x, const float* __restrict__ Wa,
                            const float* __restrict__ ba, float* __restrict__ out_xt) {
    int b = blockIdx.x;
    int c = threadIdx.x;
    __shared__ float wx[LL];
    __shared__ float red[CC];
    if (c < LL) wx[c] = Wa[2 * HH + c];
    __syncthreads();

    const float* xb = x + (size_t)b * LL * CC;
    float s = 0.f;
#pragma unroll 4
    for (int l = 0; l < LL; l++) s += xb[l * CC + c] * wx[l];
    s += ba[0];

    red[c] = s; __syncthreads();
#pragma unroll
    for (int st = 128; st > 0; st >>= 1) {
        if (c < st) red[c] = fmaxf(red[c], red[c + st]);
        __syncthreads();
    }
    float m = red[0];
    __syncthreads();
    float e = expf(s - m);
    red[c] = e; __syncthreads();
#pragma unroll
    for (int st = 128; st > 0; st >>= 1) {
        if (c < st) red[c] += red[c + st];
        __syncthreads();
    }
    float alpha = e / red[0];

    float* ob = out_xt + (size_t)b * LL * CC;
#pragma unroll 4
    for (int l = 0; l < LL; l++) ob[l * CC + c] = alpha * xb[l * CC + c];
}

// ---------------- combined bias row: bih + bhm + (bmx+bmh)@Whm --------------------
__global__ void bias_comb(const float* __restrict__ bih, const float* __restrict__ bhm,
                          const float* __restrict__ bmx, const float* __restrict__ bmh,
                          const float* __restrict__ Whm) {
    __shared__ float bm[HH];
    int tid = threadIdx.x;
    for (int i = tid; i < HH; i += 256) bm[i] = bmx[i] + bmh[i];
    __syncthreads();
    int j = blockIdx.x * 256 + tid;
    float s = bih[j] + bhm[j];
#pragma unroll 8
    for (int k = 0; k < HH; k++) s += bm[k] * Whm[(size_t)k * G4H + j];
    g_biasc[j] = s;
}

// ---------------- stacked weight SGEMM: [Wmx;Wmh] @ Whm -> {Wcomb, W2} -----------
#define BM2 64
#define BN 128
#define BK 16

__global__ __launch_bounds__(256, 2) void sgemm_w(
    const float* __restrict__ Wmx, const float* __restrict__ Wmh,
    const float* __restrict__ Whm, const float* __restrict__ Wih,
    float* __restrict__ Wcomb, float* __restrict__ W2) {
    __shared__ alignas(16) float As[BK][BM2 + 4];
    __shared__ alignas(16) float Bs[BK][BN];

    int tid = threadIdx.x;
    int bm = blockIdx.y * BM2;
    int bn = blockIdx.x * BN;
    int tx = tid & 15, ty = tid >> 4;
    int row = ty * 4, col = tx * 8;

    const int lr = tid >> 2;
    const int lq = (tid & 3) << 2;
    int r_glob = bm + lr;
    const float* Asrc = (r_glob < CC) ? (Wmx + (size_t)r_glob * HH)
                                      : (Wmh + (size_t)(r_glob - CC) * HH);

    ull acc[4][4];
#pragma unroll
    for (int i = 0; i < 4; i++)
#pragma unroll
        for (int j = 0; j < 4; j++) acc[i][j] = 0ULL;

    for (int k0 = 0; k0 < HH; k0 += BK) {
        {
            float4 v = *(const float4*)(Asrc + k0 + lq);
            As[lq + 0][lr] = v.x; As[lq + 1][lr] = v.y;
            As[lq + 2][lr] = v.z; As[lq + 3][lr] = v.w;
        }
#pragma unroll
        for (int i = 0; i < 2; i++) {
            int idx = tid + i * 256;
            int r = idx >> 5;
            int c = (idx & 31) << 2;
            *(float4*)&Bs[r][c] = *(const float4*)(Whm + (size_t)(k0 + r) * G4H + bn + c);
        }
        __syncthreads();
#pragma unroll
        for (int kk = 0; kk < BK; kk++) {
            float4 a0 = *(const float4*)&As[kk][row];
            float4 b0 = *(const float4*)&Bs[kk][col];
            float4 b1 = *(const float4*)&Bs[kk][col + 4];
            ull bp0 = pk2(b0.x, b0.y), bp1 = pk2(b0.z, b0.w);
            ull bp2 = pk2(b1.x, b1.y), bp3 = pk2(b1.z, b1.w);
            float av[4] = {a0.x, a0.y, a0.z, a0.w};
#pragma unroll
            for (int i = 0; i < 4; i++) {
                ull ap = pk2(av[i], av[i]);
                fma2(acc[i][0], ap, bp0);
                fma2(acc[i][1], ap, bp1);
                fma2(acc[i][2], ap, bp2);
                fma2(acc[i][3], ap, bp3);
            }
        }
        __syncthreads();
    }

#pragma unroll
    for (int i = 0; i < 4; i++) {
        int rg = bm + row + i;
        float o[8];
#pragma unroll
        for (int j = 0; j < 4; j++) upk2(acc[i][j], o[2 * j], o[2 * j + 1]);
        float* outp;
        if (rg < CC) {
            size_t off = (size_t)rg * G4H + bn + col;
            float4 c0 = *(const float4*)(Wih + off);
            float4 c1 = *(const float4*)(Wih + off + 4);
            o[0] += c0.x; o[1] += c0.y; o[2] += c0.z; o[3] += c0.w;
            o[4] += c1.x; o[5] += c1.y; o[6] += c1.z; o[7] += c1.w;
            outp = Wcomb + off;
        } else {
            outp = W2 + (size_t)(rg - CC) * G4H + bn + col;
        }
        *(float4*)(outp) = make_float4(o[0], o[1], o[2], o[3]);
        *(float4*)(outp + 4) = make_float4(o[4], o[5], o[6], o[7]);
    }
}

// ---------------- bf16 split conversions ------------------------------------------
__device__ __forceinline__ uint32_t pkbf2(float a, float b) {
    __nv_bfloat162 h2 = __floats2bfloat162_rn(a, b);
    return *(uint32_t*)&h2;
}

// x [32768 x 256] fp32 -> A2 [32768 x 768] bf16 (cols: [hi | hi | lo])
__global__ void conv_x(const float* __restrict__ x) {
    int i = blockIdx.x * blockDim.x + threadIdx.x;
    int m = i >> 6;
    int c = (i & 63) << 2;
    float4 v = *(const float4*)(x + (size_t)m * CC + c);
    float h0 = __bfloat162float(__float2bfloat16(v.x));
    float h1 = __bfloat162float(__float2bfloat16(v.y));
    float h2 = __bfloat162float(__float2bfloat16(v.z));
    float h3 = __bfloat162float(__float2bfloat16(v.w));
    uint2 hi = make_uint2(pkbf2(v.x, v.y), pkbf2(v.z, v.w));
    uint2 lo = make_uint2(pkbf2(v.x - h0, v.y - h1), pkbf2(v.z - h2, v.w - h3));
    __nv_bfloat16* row = g_A2 + (size_t)m * 768;
    *(uint2*)(row + c) = hi;
    *(uint2*)(row + 256 + c) = hi;
    *(uint2*)(row + 512 + c) = lo;
}

// Wcomb [256 x 2048 orig] -> B2 [2048 interleaved-n x 768] bf16 (k: [hi | lo | hi])
__global__ void conv_w() {
    int i = blockIdx.x * blockDim.x + threadIdx.x;
    int n = i >> 6;                       // interleaved col: n = h*4+g
    int k4 = (i & 63) << 2;
    int corig = (n & 3) * HH + (n >> 2);  // original col: g*HH+h
    float v0 = g_Wcomb[(size_t)(k4 + 0) * G4H + corig];
    float v1 = g_Wcomb[(size_t)(k4 + 1) * G4H + corig];
    float v2 = g_Wcomb[(size_t)(k4 + 2) * G4H + corig];
    float v3 = g_Wcomb[(size_t)(k4 + 3) * G4H + corig];
    float h0 = __bfloat162float(__float2bfloat16(v0));
    float h1 = __bfloat162float(__float2bfloat16(v1));
    float h2 = __bfloat162float(__float2bfloat16(v2));
    float h3 = __bfloat162float(__float2bfloat16(v3));
    uint2 hi = make_uint2(pkbf2(v0, v1), pkbf2(v2, v3));
    uint2 lo = make_uint2(pkbf2(v0 - h0, v1 - h1), pkbf2(v2 - h2, v3 - h3));
    __nv_bfloat16* row = g_B2 + (size_t)n * 768;
    *(uint2*)(row + k4) = hi;
    *(uint2*)(row + 256 + k4) = lo;
    *(uint2*)(row + 512 + k4) = hi;
}

// W2 [512 k x 2048 orig] -> W2T hi/lo [2048 interleaved-n x 512 k] bf16
__global__ void conv_w2t() {
    int i = blockIdx.x * blockDim.x + threadIdx.x;  // (n, k-group of 4)
    int n = i >> 7;                                 // 512/4 = 128 groups
    int k4 = (i & 127) << 2;
    int corig = (n & 3) * HH + (n >> 2);
    float v0 = g_W2[(size_t)(k4 + 0) * G4H + corig];
    float v1 = g_W2[(size_t)(k4 + 1) * G4H + corig];
    float v2 = g_W2[(size_t)(k4 + 2) * G4H + corig];
    float v3 = g_W2[(size_t)(k4 + 3) * G4H + corig];
    float h0 = __bfloat162float(__float2bfloat16(v0));
    float h1 = __bfloat162float(__float2bfloat16(v1));
    float h2 = __bfloat162float(__float2bfloat16(v2));
    float h3 = __bfloat162float(__float2bfloat16(v3));
    *(uint2*)(g_W2Thi + (size_t)n * HH + k4) = make_uint2(pkbf2(v0, v1), pkbf2(v2, v3));
    *(uint2*)(g_W2Tlo + (size_t)n * HH + k4) =
        make_uint2(pkbf2(v0 - h0, v1 - h1), pkbf2(v2 - h2, v3 - h3));
}

// ---------------- HMMA GEMM: preG2 = A2 @ B2^T (R11 proven 2-buffer) -------------
#define GSM_BUF 32768   // A 16KB + B 16KB per buffer

__global__ __launch_bounds__(256) void gemm_mma(float* __restrict__ Cm) {
    extern __shared__ char sm[];
    uint32_t sb = smem_u32(sm);
    const int tid = threadIdx.x;
    const int wid = tid >> 5, lane = tid & 31;
    const int bn = blockIdx.x * 128, bm = blockIdx.y * 128;
    const int wm0 = (wid & 1) * 64, wn0 = (wid >> 1) * 32;

    float C[4][4][4];
#pragma unroll
    for (int mi = 0; mi < 4; mi++)
#pragma unroll
        for (int ni = 0; ni < 4; ni++)
#pragma unroll
            for (int e = 0; e < 4; e++) C[mi][ni][e] = 0.f;

    const int lr = tid >> 3;
    const int lk8 = tid & 7;
#define ISSUE(kc) do { \
        int _buf = (kc) & 1; \
        uint32_t _Ab = sb + _buf * GSM_BUF; \
        uint32_t _Bb = _Ab + 16384; \
        _Pragma("unroll") \
        for (int _it = 0; _it < 4; _it++) { \
            int _r = lr + _it * 32; \
            uint32_t _sw = (uint32_t)(_r * 128 + ((lk8 ^ (_r & 7)) << 4)); \
            cpasync16(_Ab + _sw, g_A2 + (size_t)(bm + _r) * 768 + (kc) * 64 + lk8 * 8); \
            cpasync16(_Bb + _sw, g_B2 + (size_t)(bn + _r) * 768 + (kc) * 64 + lk8 * 8); \
        } \
        CP_COMMIT(); \
    } while (0)

    ISSUE(0);
    ISSUE(1);

    const int lmid = lane >> 3;
    const int lrow8 = lane & 7;

    for (int kc = 0; kc < 12; kc++) {
        int buf = kc & 1;
        if (kc < 11) { CP_WAIT1(); } else { CP_WAIT0(); }
        __syncthreads();
        uint32_t Ab = sb + buf * GSM_BUF;
        uint32_t Bb = Ab + 16384;
#pragma unroll
        for (int ks = 0; ks < 4; ks++) {
            uint32_t a[4][4], b[2][4];
#pragma unroll
            for (int mi = 0; mi < 4; mi++) {
                int row = wm0 + mi * 16 + ((lmid & 1) << 3) + lrow8;
                int k8 = ks * 2 + (lmid >> 1);
                ldm_x4(a[mi][0], a[mi][1], a[mi][2], a[mi][3],
                       Ab + row * 128 + ((k8 ^ (row & 7)) << 4));
            }
#pragma unroll
            for (int nb = 0; nb < 2; nb++) {
                int row = wn0 + nb * 16 + ((lmid >> 1) << 3) + lrow8;
                int k8 = ks * 2 + (lmid & 1);
                ldm_x4(b[nb][0], b[nb][1], b[nb][2], b[nb][3],
                       Bb + row * 128 + ((k8 ^ (row & 7)) << 4));
            }
#pragma unroll
            for (int mi = 0; mi < 4; mi++)
#pragma unroll
                for (int ni = 0; ni < 4; ni++)
                    mma16816(C[mi][ni], a[mi],
                             b[ni >> 1][(ni & 1) * 2], b[ni >> 1][(ni & 1) * 2 + 1]);
        }
        __syncthreads();
        if (kc + 2 < 12) ISSUE(kc + 2);
    }

    const int qid = lane >> 2, tq = lane & 3;
#pragma unroll
    for (int ni = 0; ni < 4; ni++) {
        int col = bn + wn0 + ni * 8 + tq * 2;
#pragma unroll
        for (int mi = 0; mi < 4; mi++) {
            int row = bm + wm0 + mi * 16 + qid;
            *(float2*)(Cm + (size_t)row * G4H + col) = make_float2(C[mi][ni][0], C[mi][ni][1]);
            *(float2*)(Cm + (size_t)(row + 8) * G4H + col) = make_float2(C[mi][ni][2], C[mi][ni][3]);
        }
    }
#undef ISSUE
}

// ---------------- HMMA persistent recurrence (R11 + staged coalesced stores) ------
// 128 CTAs: x = n-tile (64 interleaved gate cols = 16 h), y = b-tile (64 rows).
// W2T hi/lo 128KB; 4 slots x 32KB A, 3-deep. Epilogue stages h/C in buffer-2
// region, then stores wide & coalesced (bit-identical data movement).
#define LSM_BLO 65536
#define LSM_A   131072
#define LSM_TOT (131072 + 3 * 32768)   // 229376 bytes

__global__ __launch_bounds__(256, 1) void lstm_mma(
    const float* __restrict__ preG2, float* __restrict__ out_h, float* __restrict__ out_c) {
    extern __shared__ char sm[];
    uint32_t sb = smem_u32(sm);
    const int tid = threadIdx.x;
    const int wid = tid >> 5, lane = tid & 31;
    const int nt = blockIdx.x, bt = blockIdx.y;
    const int b0 = bt * 64;
    const int n0 = nt * 64;
    const int wm = (wid & 1) * 32, wn = (wid >> 1) * 16;
    const int lmid = lane >> 3, lrow8 = lane & 7;
    const int qid = lane >> 2, tq = lane & 3;
    const int parity = tq & 1;
    const int lr = tid >> 3, lk8 = tid & 7;

    // staging area = A buffer 2 (free after slot 3; rewritten 2 syncs into next step)
    float* stg = (float*)(sm + LSM_A + 2 * 32768);          // [2][64][20] floats (h, C)
    __nv_bfloat16* stg16 = (__nv_bfloat16*)(sm + LSM_A + 2 * 32768 + 10240); // [2][64][16]

    // load W2T slices (hi/lo) into SMEM once: 64 n-rows x 512 k, swizzled
    for (int i = tid; i < 4096; i += 256) {
        int r = i >> 6, c = i & 63;
        uint32_t dst = (uint32_t)(r * 1024 + (((c & 56) | ((c ^ r) & 7)) << 4));
        *(uint4*)(sm + dst) = *(const uint4*)(g_W2Thi + (size_t)(n0 + r) * HH + c * 8);
        *(uint4*)(sm + LSM_BLO + dst) = *(const uint4*)(g_W2Tlo + (size_t)(n0 + r) * HH + c * 8);
    }

    int bb[2], hh[2];
#pragma unroll
    for (int mi = 0; mi < 2; mi++) bb[mi] = b0 + wm + mi * 16 + qid + parity * 8;
#pragma unroll
    for (int ni = 0; ni < 2; ni++) hh[ni] = nt * 16 + (wid >> 1) * 4 + ni * 2 + (tq >> 1);

    float bgv[2][4];
#pragma unroll
    for (int ni = 0; ni < 2; ni++)
#pragma unroll
        for (int g = 0; g < 4; g++) bgv[ni][g] = g_biasc[g * HH + hh[ni]];

    float Creg[2][2] = {{0.f, 0.f}, {0.f, 0.f}};
    __syncthreads();

#define AISSUE3(s) do { \
        uint32_t _ab = sb + LSM_A + ((s) % 3) * 32768; \
        const __nv_bfloat16* _src = ((s) < 2) ? g_hhi : g_hlo; \
        int _kb = ((s) & 1) * 256; \
        _Pragma("unroll") \
        for (int _it = 0; _it < 8; _it++) { \
            int _half = _it >> 1; \
            int _r = lr + (_it & 1) * 32; \
            cpasync16(_ab + _half * 8192 + (uint32_t)(_r * 128 + ((lk8 ^ (_r & 7)) << 4)), \
                      _src + (size_t)(b0 + _r) * HH + _kb + _half * 64 + lk8 * 8); \
        } \
        CP_COMMIT(); \
    } while (0)

    // prefetch preG2 gate vectors for t=0
    float4 pv[2][2];
#pragma unroll
    for (int mi = 0; mi < 2; mi++)
#pragma unroll
        for (int ni = 0; ni < 2; ni++)
            pv[mi][ni] = __ldg((const float4*)(preG2 + ((size_t)bb[mi] * LL + 0) * G4H + hh[ni] * 4));

    for (int t = 0; t < LL; t++) {
        float C[2][2][4];
#pragma unroll
        for (int mi = 0; mi < 2; mi++)
#pragma unroll
            for (int ni = 0; ni < 2; ni++)
#pragma unroll
                for (int e = 0; e < 4; e++) C[mi][ni][e] = 0.f;

        if (t > 0) {
            AISSUE3(0);
            AISSUE3(1);
            AISSUE3(2);
            for (int s = 0; s < 4; s++) {
                if (s == 0) { CP_WAIT2(); } else if (s < 3) { CP_WAIT1(); } else { CP_WAIT0(); }
                __syncthreads();
                if (s == 1) AISSUE3(3);
                uint32_t Ab = sb + LSM_A + (s % 3) * 32768;
                bool dual = (s < 2);
#pragma unroll
                for (int half = 0; half < 4; half++) {
                    uint32_t Abh = Ab + half * 8192;
                    int kc = (s & 1) * 4 + half;   // 0..7
#pragma unroll
                    for (int ks = 0; ks < 4; ks++) {
                        uint32_t a[2][4];
#pragma unroll
                        for (int mi = 0; mi < 2; mi++) {
                            int row = wm + mi * 16 + ((lmid & 1) << 3) + lrow8;
                            int k8 = ks * 2 + (lmid >> 1);
                            ldm_x4(a[mi][0], a[mi][1], a[mi][2], a[mi][3],
                                   Abh + row * 128 + ((k8 ^ (row & 7)) << 4));
                        }
                        int brow = wn + ((lmid >> 1) << 3) + lrow8;
                        int k8b = kc * 8 + ks * 2 + (lmid & 1);
                        uint32_t boff = (uint32_t)(brow * 1024 +
                            (((k8b & 56) | ((k8b ^ brow) & 7)) << 4));
                        uint32_t bh[4];
                        ldm_x4(bh[0], bh[1], bh[2], bh[3], sb + boff);
#pragma unroll
                        for (int mi = 0; mi < 2; mi++)
#pragma unroll
                            for (int ni = 0; ni < 2; ni++)
                                mma16816(C[mi][ni], a[mi], bh[ni * 2], bh[ni * 2 + 1]);
                        if (dual) {
                            uint32_t bl[4];
                            ldm_x4(bl[0], bl[1], bl[2], bl[3], sb + LSM_BLO + boff);
#pragma unroll
                            for (int mi = 0; mi < 2; mi++)
#pragma unroll
                                for (int ni = 0; ni < 2; ni++)
                                    mma16816(C[mi][ni], a[mi], bl[ni * 2], bl[ni * 2 + 1]);
                        }
                    }
                }
            }
        }

        // epilogue: parity exchange + cell update -> stage in SMEM
#pragma unroll
        for (int mi = 0; mi < 2; mi++) {
#pragma unroll
            for (int ni = 0; ni < 2; ni++) {
                float s0 = parity ? C[mi][ni][0] : C[mi][ni][2];
                float s1 = parity ? C[mi][ni][1] : C[mi][ni][3];
                float r0 = __shfl_xor_sync(0xffffffffu, s0, 1);
                float r1 = __shfl_xor_sync(0xffffffffu, s1, 1);
                float gi, gf, gg, go;
                if (!parity) { gi = C[mi][ni][0]; gf = C[mi][ni][1]; gg = r0; go = r1; }
                else         { gi = r0; gf = r1; gg = C[mi][ni][2]; go = C[mi][ni][3]; }
                gi += pv[mi][ni].x + bgv[ni][0];
                gf += pv[mi][ni].y + bgv[ni][1];
                gg += pv[mi][ni].z + bgv[ni][2];
                go += pv[mi][ni].w + bgv[ni][3];

                float Cn = sigma(gf) * Creg[mi][ni] + sigma(gi) * tanha(gg);
                float hn = sigma(go) * tanha(Cn);
                Creg[mi][ni] = Cn;

                int blc = wm + mi * 16 + qid + parity * 8;          // 0..63
                int hl = (wid >> 1) * 4 + ni * 2 + (tq >> 1);       // 0..15
                stg[blc * 20 + hl] = hn;
                stg[1280 + blc * 20 + hl] = Cn;
                __nv_bfloat16 hb = __float2bfloat16(hn);
                stg16[blc * 16 + hl] = hb;
                stg16[1024 + blc * 16 + hl] = __float2bfloat16(hn - __bfloat162float(hb));
            }
        }
        __syncthreads();

        // coalesced h hi/lo publish (critical path for next step's consumers)
        {
            int i2 = tid & 127;
            int b_l = i2 >> 1, hf = i2 & 1;
            __nv_bfloat16* gdst = (tid < 128) ? g_hhi : g_hlo;
            const __nv_bfloat16* ssrc = stg16 + ((tid < 128) ? 0 : 1024);
            *(uint4*)(gdst + (size_t)(b0 + b_l) * HH + nt * 16 + hf * 8) =
                *(const uint4*)(ssrc + b_l * 16 + hf * 8);
        }
        // coalesced out_h / out_c stores
#pragma unroll
        for (int j = 0; j < 2; j++) {
            int idx = tid * 2 + j;            // 0..511
            int arr = idx >> 8, r = idx & 255;
            int blc = r >> 2, h4 = (r & 3) * 4;
            float4 v = *(const float4*)(stg + arr * 1280 + blc * 20 + h4);
            float* dst = (arr ? out_c : out_h) +
                         ((size_t)(b0 + blc) * LL + t) * HH + nt * 16 + h4;
            __stcs((float4*)dst, v);
        }

        // per-b-tile group barrier; prefetch next step's preG2 behind the wait
        if (t != LL - 1) {
#pragma unroll
            for (int mi = 0; mi < 2; mi++)
#pragma unroll
                for (int ni = 0; ni < 2; ni++)
                    pv[mi][ni] = __ldg((const float4*)(preG2 +
                        ((size_t)bb[mi] * LL + (t + 1)) * G4H + hh[ni] * 4));
            __threadfence();
            __syncthreads();
            if (tid == 0) {
                atomicAdd((unsigned*)&g_barg[bt * 64], 1u);
                unsigned tgt = 32u * (unsigned)(t + 1);
                while (g_barg[bt * 64] < tgt) { __nanosleep(64); }
            }
            __syncthreads();
        }
    }
#undef AISSUE3
}

// ---------------- launch ----------------
extern "C" void kernel_launch(void* const* d_in, const int* in_sizes, int n_in,
                              void* d_out, int out_size) {
    const float* x   = (const float*)d_in[0];
    const float* Wih = (const float*)d_in[1];
    const float* bih = (const float*)d_in[2];
    const float* Wmx = (const float*)d_in[3];
    const float* bmx = (const float*)d_in[4];
    const float* Wmh = (const float*)d_in[5];
    const float* bmh = (const float*)d_in[6];
    const float* Whm = (const float*)d_in[7];
    const float* bhm = (const float*)d_in[8];
    const float* Wa  = (const float*)d_in[9];
    const float* ba  = (const float*)d_in[10];

    float* out    = (float*)d_out;
    float* out_h  = out;
    float* out_c  = out + (size_t)BB * LL * HH;
    float* out_xt = out + (size_t)2 * BB * LL * HH;

    float *preG2, *W2, *Wcomb;
    cudaGetSymbolAddress((void**)&preG2, g_preG2);
    cudaGetSymbolAddress((void**)&W2, g_W2);
    cudaGetSymbolAddress((void**)&Wcomb, g_Wcomb);

    // (1) stacked weight GEMM: [Wmx;Wmh] @ Whm -> {Wcomb(+Wih), W2}
    sgemm_w<<<dim3(G4H / BN, (CC + HH) / BM2), 256>>>(Wmx, Wmh, Whm, Wih, Wcomb, W2);
    // (2) Wcomb -> B2 (interleaved n, split bf16)
    conv_w<<<(G4H * 64) / 256, 256>>>();
    // (3) X -> A2 (split bf16)
    conv_x<<<(BB * LL * CC / 4) / 256, 256>>>(x);
    // (4) preG2 = A2 @ B2^T  (2-buffer proven pipeline)
    cudaFuncSetAttribute(gemm_mma, cudaFuncAttributeMaxDynamicSharedMemorySize, 2 * GSM_BUF);
    gemm_mma<<<dim3(G4H / 128, (BB * LL) / 128), 256, 2 * GSM_BUF>>>(preG2);

    // (5) barrier reset
    zero_init<<<1, 32>>>();
    // (6) attention path
    attn_xtilde<<<BB, 256>>>(x, Wa, ba, out_xt);
    // (7) combined bias row (orig layout)
    bias_comb<<<G4H / 256, 256>>>(bih, bhm, bmx, bmh, Whm);
    // (8) W2 -> W2T hi/lo (interleaved n, split bf16)
    conv_w2t<<<(G4H * 128) / 256, 256>>>();

    // (9) persistent HMMA recurrence: R11 pipeline + staged coalesced stores
    cudaFuncSetAttribute(lstm_mma, cudaFuncAttributeMaxDynamicSharedMemorySize, LSM_TOT);
    lstm_mma<<<dim3(32, 4), 256, LSM_TOT>>>(preG2, out_h, out_c);
}

// round 14
// speedup vs baseline: 1.3514x; 1.2040x over previous
#include <cuda_runtime.h>
#include <cuda_bf16.h>
#include <math.h>
#include <stdint.h>
#include <string.h>

#define BB 256
#define LL 128
#define CC 256
#define HH 512
#define G4H 2048   // 4*HH

// ---------------- scratch (device globals: no allocation allowed) ----------------
__device__ float g_preG2[(size_t)BB * LL * G4H];  // 32768 x 2048, cols interleaved h*4+g
__device__ float g_W2[HH * G4H];                  // Wmh @ Whm (orig col layout)
__device__ float g_Wcomb[CC * G4H];               // Wih + Wmx@Whm (orig col layout)
__device__ float g_biasc[G4H];                    // combined bias row (orig layout)
__device__ volatile unsigned g_barg[256];         // 4 group barrier counters (stride 64)
__device__ alignas(256) __nv_bfloat16 g_A2[(size_t)BB * LL * 768];  // [Xhi|Xhi|Xlo]
__device__ alignas(256) __nv_bfloat16 g_B2[(size_t)G4H * 768];      // [n_il][Whi;Wlo;Whi]
__device__ alignas(256) __nv_bfloat16 g_W2Thi[(size_t)G4H * HH];    // [n_il][k] hi
__device__ alignas(256) __nv_bfloat16 g_W2Tlo[(size_t)G4H * HH];    // [n_il][k] lo
__device__ alignas(256) __nv_bfloat16 g_hhi[BB * HH];               // h bf16 hi [b][k]
__device__ alignas(256) __nv_bfloat16 g_hlo[BB * HH];               // h bf16 lo [b][k]

typedef unsigned long long ull;

// ---------------- helpers ---------------------------------------------------------
__device__ __forceinline__ ull pk2(float x, float y) {
    ull r; asm("mov.b64 %0, {%1, %2};" : "=l"(r) : "f"(x), "f"(y)); return r;
}
__device__ __forceinline__ void upk2(ull v, float& x, float& y) {
    asm("mov.b64 {%0, %1}, %2;" : "=f"(x), "=f"(y) : "l"(v));
}
__device__ __forceinline__ void fma2(ull& d, ull a, ull b) {
    asm("fma.rn.f32x2 %0, %1, %2, %0;" : "+l"(d) : "l"(a), "l"(b));
}
__device__ __forceinline__ float tanha(float x) {
    float y; asm("tanh.approx.f32 %0, %1;" : "=f"(y) : "f"(x)); return y;
}
__device__ __forceinline__ float sigma(float x) {
    return fmaf(tanha(x * 0.5f), 0.5f, 0.5f);
}
__device__ __forceinline__ uint32_t smem_u32(const void* p) {
    uint32_t a;
    asm("{ .reg .u64 t; cvta.to.shared.u64 t, %1; cvt.u32.u64 %0, t; }" : "=r"(a) : "l"(p));
    return a;
}
__device__ __forceinline__ void ldm_x4(uint32_t& r0, uint32_t& r1, uint32_t& r2,
                                       uint32_t& r3, uint32_t addr) {
    asm volatile("ldmatrix.sync.aligned.m8n8.x4.shared.b16 {%0,%1,%2,%3}, [%4];"
                 : "=r"(r0), "=r"(r1), "=r"(r2), "=r"(r3) : "r"(addr));
}
__device__ __forceinline__ void mma16816(float* d, const uint32_t* a, uint32_t b0, uint32_t b1) {
    asm volatile("mma.sync.aligned.m16n8k16.row.col.f32.bf16.bf16.f32 "
                 "{%0,%1,%2,%3}, {%4,%5,%6,%7}, {%8,%9}, {%0,%1,%2,%3};"
                 : "+f"(d[0]), "+f"(d[1]), "+f"(d[2]), "+f"(d[3])
                 : "r"(a[0]), "r"(a[1]), "r"(a[2]), "r"(a[3]), "r"(b0), "r"(b1));
}
__device__ __forceinline__ void cpasync16(uint32_t dst, const void* src) {
    asm volatile("cp.async.cg.shared.global [%0], [%1], 16;" :: "r"(dst), "l"(src) : "memory");
}
#define CP_COMMIT() asm volatile("cp.async.commit_group;" ::: "memory")
#define CP_WAIT2()  asm volatile("cp.async.wait_group 2;" ::: "memory")
#define CP_WAIT1()  asm volatile("cp.async.wait_group 1;" ::: "memory")
#define CP_WAIT0()  asm volatile("cp.async.wait_group 0;" ::: "memory")

// ---------------- init ------------------------------------------------------------
__global__ void zero_init() {
    int i = threadIdx.x;
    if (i < 4) g_barg[i * 64] = 0u;
}

// ---------------- attention: softmax is time-invariant ---------------------------
__global__ void attn_xtilde(const float* __restrict__ x, const float* __restrict__ Wa,
                            const float* __restrict__ ba, float* __restrict__ out_xt) {
    int b = blockIdx.x;
    int c = threadIdx.x;
    __shared__ float wx[LL];
    __shared__ float red[CC];
    if (c < LL) wx[c] = Wa[2 * HH + c];
    __syncthreads();

    const float* xb = x + (size_t)b * LL * CC;
    float s = 0.f;
#pragma unroll 4
    for (int l = 0; l < LL; l++) s += xb[l * CC + c] * wx[l];
    s += ba[0];

    red[c] = s; __syncthreads();
#pragma unroll
    for (int st = 128; st > 0; st >>= 1) {
        if (c < st) red[c] = fmaxf(red[c], red[c + st]);
        __syncthreads();
    }
    float m = red[0];
    __syncthreads();
    float e = expf(s - m);
    red[c] = e; __syncthreads();
#pragma unroll
    for (int st = 128; st > 0; st >>= 1) {
        if (c < st) red[c] += red[c + st];
        __syncthreads();
    }
    float alpha = e / red[0];

    float* ob = out_xt + (size_t)b * LL * CC;
#pragma unroll 4
    for (int l = 0; l < LL; l++) ob[l * CC + c] = alpha * xb[l * CC + c];
}

// ---------------- combined bias row: bih + bhm + (bmx+bmh)@Whm --------------------
__global__ void bias_comb(const float* __restrict__ bih, const float* __restrict__ bhm,
                          const float* __restrict__ bmx, const float* __restrict__ bmh,
                          const float* __restrict__ Whm) {
    __shared__ float bm[HH];
    int tid = threadIdx.x;
    for (int i = tid; i < HH; i += 256) bm[i] = bmx[i] + bmh[i];
    __syncthreads();
    int j = blockIdx.x * 256 + tid;
    float s = bih[j] + bhm[j];
#pragma unroll 8
    for (int k = 0; k < HH; k++) s += bm[k] * Whm[(size_t)k * G4H + j];
    g_biasc[j] = s;
}

// ---------------- stacked weight SGEMM: [Wmx;Wmh] @ Whm -> {Wcomb, W2} -----------
#define BM2 64
#define BN 128
#define BK 16

__global__ __launch_bounds__(256, 2) void sgemm_w(
    const float* __restrict__ Wmx, const float* __restrict__ Wmh,
    const float* __restrict__ Whm, const float* __restrict__ Wih,
    float* __restrict__ Wcomb, float* __restrict__ W2) {
    __shared__ alignas(16) float As[BK][BM2 + 4];
    __shared__ alignas(16) float Bs[BK][BN];

    int tid = threadIdx.x;
    int bm = blockIdx.y * BM2;
    int bn = blockIdx.x * BN;
    int tx = tid & 15, ty = tid >> 4;
    int row = ty * 4, col = tx * 8;

    const int lr = tid >> 2;
    const int lq = (tid & 3) << 2;
    int r_glob = bm + lr;
    const float* Asrc = (r_glob < CC) ? (Wmx + (size_t)r_glob * HH)
                                      : (Wmh + (size_t)(r_glob - CC) * HH);

    ull acc[4][4];
#pragma unroll
    for (int i = 0; i < 4; i++)
#pragma unroll
        for (int j = 0; j < 4; j++) acc[i][j] = 0ULL;

    for (int k0 = 0; k0 < HH; k0 += BK) {
        {
            float4 v = *(const float4*)(Asrc + k0 + lq);
            As[lq + 0][lr] = v.x; As[lq + 1][lr] = v.y;
            As[lq + 2][lr] = v.z; As[lq + 3][lr] = v.w;
        }
#pragma unroll
        for (int i = 0; i < 2; i++) {
            int idx = tid + i * 256;
            int r = idx >> 5;
            int c = (idx & 31) << 2;
            *(float4*)&Bs[r][c] = *(const float4*)(Whm + (size_t)(k0 + r) * G4H + bn + c);
        }
        __syncthreads();
#pragma unroll
        for (int kk = 0; kk < BK; kk++) {
            float4 a0 = *(const float4*)&As[kk][row];
            float4 b0 = *(const float4*)&Bs[kk][col];
            float4 b1 = *(const float4*)&Bs[kk][col + 4];
            ull bp0 = pk2(b0.x, b0.y), bp1 = pk2(b0.z, b0.w);
            ull bp2 = pk2(b1.x, b1.y), bp3 = pk2(b1.z, b1.w);
            float av[4] = {a0.x, a0.y, a0.z, a0.w};
#pragma unroll
            for (int i = 0; i < 4; i++) {
                ull ap = pk2(av[i], av[i]);
                fma2(acc[i][0], ap, bp0);
                fma2(acc[i][1], ap, bp1);
                fma2(acc[i][2], ap, bp2);
                fma2(acc[i][3], ap, bp3);
            }
        }
        __syncthreads();
    }

#pragma unroll
    for (int i = 0; i < 4; i++) {
        int rg = bm + row + i;
        float o[8];
#pragma unroll
        for (int j = 0; j < 4; j++) upk2(acc[i][j], o[2 * j], o[2 * j + 1]);
        float* outp;
        if (rg < CC) {
            size_t off = (size_t)rg * G4H + bn + col;
            float4 c0 = *(const float4*)(Wih + off);
            float4 c1 = *(const float4*)(Wih + off + 4);
            o[0] += c0.x; o[1] += c0.y; o[2] += c0.z; o[3] += c0.w;
            o[4] += c1.x; o[5] += c1.y; o[6] += c1.z; o[7] += c1.w;
            outp = Wcomb + off;
        } else {
            outp = W2 + (size_t)(rg - CC) * G4H + bn + col;
        }
        *(float4*)(outp) = make_float4(o[0], o[1], o[2], o[3]);
        *(float4*)(outp + 4) = make_float4(o[4], o[5], o[6], o[7]);
    }
}

// ---------------- bf16 split conversions ------------------------------------------
__device__ __forceinline__ uint32_t pkbf2(float a, float b) {
    __nv_bfloat162 h2 = __floats2bfloat162_rn(a, b);
    return *(uint32_t*)&h2;
}

// x [32768 x 256] fp32 -> A2 [32768 x 768] bf16 (cols: [hi | hi | lo])
__global__ void conv_x(const float* __restrict__ x) {
    int i = blockIdx.x * blockDim.x + threadIdx.x;
    int m = i >> 6;
    int c = (i & 63) << 2;
    float4 v = *(const float4*)(x + (size_t)m * CC + c);
    float h0 = __bfloat162float(__float2bfloat16(v.x));
    float h1 = __bfloat162float(__float2bfloat16(v.y));
    float h2 = __bfloat162float(__float2bfloat16(v.z));
    float h3 = __bfloat162float(__float2bfloat16(v.w));
    uint2 hi = make_uint2(pkbf2(v.x, v.y), pkbf2(v.z, v.w));
    uint2 lo = make_uint2(pkbf2(v.x - h0, v.y - h1), pkbf2(v.z - h2, v.w - h3));
    __nv_bfloat16* row = g_A2 + (size_t)m * 768;
    *(uint2*)(row + c) = hi;
    *(uint2*)(row + 256 + c) = hi;
    *(uint2*)(row + 512 + c) = lo;
}

// Wcomb [256 x 2048 orig] -> B2 [2048 interleaved-n x 768] bf16 (k: [hi | lo | hi])
__global__ void conv_w() {
    int i = blockIdx.x * blockDim.x + threadIdx.x;
    int n = i >> 6;                       // interleaved col: n = h*4+g
    int k4 = (i & 63) << 2;
    int corig = (n & 3) * HH + (n >> 2);  // original col: g*HH+h
    float v0 = g_Wcomb[(size_t)(k4 + 0) * G4H + corig];
    float v1 = g_Wcomb[(size_t)(k4 + 1) * G4H + corig];
    float v2 = g_Wcomb[(size_t)(k4 + 2) * G4H + corig];
    float v3 = g_Wcomb[(size_t)(k4 + 3) * G4H + corig];
    float h0 = __bfloat162float(__float2bfloat16(v0));
    float h1 = __bfloat162float(__float2bfloat16(v1));
    float h2 = __bfloat162float(__float2bfloat16(v2));
    float h3 = __bfloat162float(__float2bfloat16(v3));
    uint2 hi = make_uint2(pkbf2(v0, v1), pkbf2(v2, v3));
    uint2 lo = make_uint2(pkbf2(v0 - h0, v1 - h1), pkbf2(v2 - h2, v3 - h3));
    __nv_bfloat16* row = g_B2 + (size_t)n * 768;
    *(uint2*)(row + k4) = hi;
    *(uint2*)(row + 256 + k4) = lo;
    *(uint2*)(row + 512 + k4) = hi;
}

// W2 [512 k x 2048 orig] -> W2T hi/lo [2048 interleaved-n x 512 k] bf16
// tiled transpose: coalesced reads of g_W2, coalesced 8B writes of W2T.
__global__ void conv_w2t() {
    __shared__ __nv_bfloat16 shi[32][34];
    __shared__ __nv_bfloat16 slo[32][34];
    int k0 = blockIdx.x * 32;     // 16 blocks
    int c0 = blockIdx.y * 32;     // 64 blocks
    int tid = threadIdx.x;

    {   // read 32x32 fp32 tile coalesced, split to bf16 hi/lo
        int r = tid >> 3;
        int c4 = (tid & 7) * 4;
        float4 v = *(const float4*)&g_W2[(size_t)(k0 + r) * G4H + c0 + c4];
        float h0 = __bfloat162float(__float2bfloat16(v.x));
        float h1 = __bfloat162float(__float2bfloat16(v.y));
        float h2 = __bfloat162float(__float2bfloat16(v.z));
        float h3 = __bfloat162float(__float2bfloat16(v.w));
        shi[r][c4 + 0] = __float2bfloat16(v.x);
        shi[r][c4 + 1] = __float2bfloat16(v.y);
        shi[r][c4 + 2] = __float2bfloat16(v.z);
        shi[r][c4 + 3] = __float2bfloat16(v.w);
        slo[r][c4 + 0] = __float2bfloat16(v.x - h0);
        slo[r][c4 + 1] = __float2bfloat16(v.y - h1);
        slo[r][c4 + 2] = __float2bfloat16(v.z - h2);
        slo[r][c4 + 3] = __float2bfloat16(v.w - h3);
    }
    __syncthreads();
    {   // write transposed: row n = (corig&511)*4 + (corig>>9), 8B chunks
        int c = tid >> 3;
        int r4 = (tid & 7) * 4;
        int cg = c0 + c;
        int n = (cg & 511) * 4 + (cg >> 9);
        uint2 uh, ul;
        __nv_bfloat16* ph = (__nv_bfloat16*)&uh;
        __nv_bfloat16* pl = (__nv_bfloat16*)&ul;
#pragma unroll
        for (int i = 0; i < 4; i++) { ph[i] = shi[r4 + i][c]; pl[i] = slo[r4 + i][c]; }
        *(uint2*)&g_W2Thi[(size_t)n * HH + k0 + r4] = uh;
        *(uint2*)&g_W2Tlo[(size_t)n * HH + k0 + r4] = ul;
    }
}

// ---------------- HMMA GEMM: preG2 = A2 @ B2^T (R11 proven 2-buffer) -------------
#define GSM_BUF 32768   // A 16KB + B 16KB per buffer

__global__ __launch_bounds__(256) void gemm_mma(float* __restrict__ Cm) {
    extern __shared__ char sm[];
    uint32_t sb = smem_u32(sm);
    const int tid = threadIdx.x;
    const int wid = tid >> 5, lane = tid & 31;
    const int bn = blockIdx.x * 128, bm = blockIdx.y * 128;
    const int wm0 = (wid & 1) * 64, wn0 = (wid >> 1) * 32;

    float C[4][4][4];
#pragma unroll
    for (int mi = 0; mi < 4; mi++)
#pragma unroll
        for (int ni = 0; ni < 4; ni++)
#pragma unroll
            for (int e = 0; e < 4; e++) C[mi][ni][e] = 0.f;

    const int lr = tid >> 3;
    const int lk8 = tid & 7;
#define ISSUE(kc) do { \
        int _buf = (kc) & 1; \
        uint32_t _Ab = sb + _buf * GSM_BUF; \
        uint32_t _Bb = _Ab + 16384; \
        _Pragma("unroll") \
        for (int _it = 0; _it < 4; _it++) { \
            int _r = lr + _it * 32; \
            uint32_t _sw = (uint32_t)(_r * 128 + ((lk8 ^ (_r & 7)) << 4)); \
            cpasync16(_Ab + _sw, g_A2 + (size_t)(bm + _r) * 768 + (kc) * 64 + lk8 * 8); \
            cpasync16(_Bb + _sw, g_B2 + (size_t)(bn + _r) * 768 + (kc) * 64 + lk8 * 8); \
        } \
        CP_COMMIT(); \
    } while (0)

    ISSUE(0);
    ISSUE(1);

    const int lmid = lane >> 3;
    const int lrow8 = lane & 7;

    for (int kc = 0; kc < 12; kc++) {
        int buf = kc & 1;
        if (kc < 11) { CP_WAIT1(); } else { CP_WAIT0(); }
        __syncthreads();
        uint32_t Ab = sb + buf * GSM_BUF;
        uint32_t Bb = Ab + 16384;
#pragma unroll
        for (int ks = 0; ks < 4; ks++) {
            uint32_t a[4][4], b[2][4];
#pragma unroll
            for (int mi = 0; mi < 4; mi++) {
                int row = wm0 + mi * 16 + ((lmid & 1) << 3) + lrow8;
                int k8 = ks * 2 + (lmid >> 1);
                ldm_x4(a[mi][0], a[mi][1], a[mi][2], a[mi][3],
                       Ab + row * 128 + ((k8 ^ (row & 7)) << 4));
            }
#pragma unroll
            for (int nb = 0; nb < 2; nb++) {
                int row = wn0 + nb * 16 + ((lmid >> 1) << 3) + lrow8;
                int k8 = ks * 2 + (lmid & 1);
                ldm_x4(b[nb][0], b[nb][1], b[nb][2], b[nb][3],
                       Bb + row * 128 + ((k8 ^ (row & 7)) << 4));
            }
#pragma unroll
            for (int mi = 0; mi < 4; mi++)
#pragma unroll
                for (int ni = 0; ni < 4; ni++)
                    mma16816(C[mi][ni], a[mi],
                             b[ni >> 1][(ni & 1) * 2], b[ni >> 1][(ni & 1) * 2 + 1]);
        }
        __syncthreads();
        if (kc + 2 < 12) ISSUE(kc + 2);
    }

    const int qid = lane >> 2, tq = lane & 3;
#pragma unroll
    for (int ni = 0; ni < 4; ni++) {
        int col = bn + wn0 + ni * 8 + tq * 2;
#pragma unroll
        for (int mi = 0; mi < 4; mi++) {
            int row = bm + wm0 + mi * 16 + qid;
            *(float2*)(Cm + (size_t)row * G4H + col) = make_float2(C[mi][ni][0], C[mi][ni][1]);
            *(float2*)(Cm + (size_t)(row + 8) * G4H + col) = make_float2(C[mi][ni][2], C[mi][ni][3]);
        }
    }
#undef ISSUE
}

// ---------------- HMMA persistent recurrence (R13 + B-hi register cache) ----------
// 128 CTAs: x = n-tile (64 interleaved gate cols = 16 h), y = b-tile (64 rows).
// W2T hi/lo 128KB; 4 slots x 32KB A, 3-deep. B-hi fragments (32 x ldm_x4) loaded
// ONCE into registers before the t-loop (step-invariant). Staged coalesced stores;
// out_h/out_c stores overlapped with barrier wait.
#define LSM_BLO 65536
#define LSM_A   131072
#define LSM_TOT (131072 + 3 * 32768)   // 229376 bytes

__global__ __launch_bounds__(256, 1) void lstm_mma(
    const float* __restrict__ preG2, float* __restrict__ out_h, float* __restrict__ out_c) {
    extern __shared__ char sm[];
    uint32_t sb = smem_u32(sm);
    const int tid = threadIdx.x;
    const int wid = tid >> 5, lane = tid & 31;
    const int nt = blockIdx.x, bt = blockIdx.y;
    const int b0 = bt * 64;
    const int n0 = nt * 64;
    const int wm = (wid & 1) * 32, wn = (wid >> 1) * 16;
    const int lmid = lane >> 3, lrow8 = lane & 7;
    const int qid = lane >> 2, tq = lane & 3;
    const int parity = tq & 1;
    const int lr = tid >> 3, lk8 = tid & 7;

    float* stg = (float*)(sm + LSM_A + 2 * 32768);
    __nv_bfloat16* stg16 = (__nv_bfloat16*)(sm + LSM_A + 2 * 32768 + 10240);

    // load W2T slices (hi/lo) into SMEM once: 64 n-rows x 512 k, swizzled
    for (int i = tid; i < 4096; i += 256) {
        int r = i >> 6, c = i & 63;
        uint32_t dst = (uint32_t)(r * 1024 + (((c & 56) | ((c ^ r) & 7)) << 4));
        *(uint4*)(sm + dst) = *(const uint4*)(g_W2Thi + (size_t)(n0 + r) * HH + c * 8);
        *(uint4*)(sm + LSM_BLO + dst) = *(const uint4*)(g_W2Tlo + (size_t)(n0 + r) * HH + c * 8);
    }

    int bb[2], hh[2];
#pragma unroll
    for (int mi = 0; mi < 2; mi++) bb[mi] = b0 + wm + mi * 16 + qid + parity * 8;
#pragma unroll
    for (int ni = 0; ni < 2; ni++) hh[ni] = nt * 16 + (wid >> 1) * 4 + ni * 2 + (tq >> 1);

    float bgv[2][4];
#pragma unroll
    for (int ni = 0; ni < 2; ni++)
#pragma unroll
        for (int g = 0; g < 4; g++) bgv[ni][g] = g_biasc[g * HH + hh[ni]];

    float Creg[2][2] = {{0.f, 0.f}, {0.f, 0.f}};
    __syncthreads();

    // ---- preload ALL B-hi fragments into registers (step-invariant) ----
    const int brow = wn + ((lmid >> 1) << 3) + lrow8;
    uint32_t Bh[8][4][4];   // [kc][ks][frag]
#pragma unroll
    for (int kc = 0; kc < 8; kc++)
#pragma unroll
        for (int ks = 0; ks < 4; ks++) {
            int k8b = kc * 8 + ks * 2 + (lmid & 1);
            uint32_t boff = (uint32_t)(brow * 1024 + (((k8b & 56) | ((k8b ^ brow) & 7)) << 4));
            ldm_x4(Bh[kc][ks][0], Bh[kc][ks][1], Bh[kc][ks][2], Bh[kc][ks][3], sb + boff);
        }

#define AISSUE3(s) do { \
        uint32_t _ab = sb + LSM_A + ((s) % 3) * 32768; \
        const __nv_bfloat16* _src = ((s) < 2) ? g_hhi : g_hlo; \
        int _kb = ((s) & 1) * 256; \
        _Pragma("unroll") \
        for (int _it = 0; _it < 8; _it++) { \
            int _half = _it >> 1; \
            int _r = lr + (_it & 1) * 32; \
            cpasync16(_ab + _half * 8192 + (uint32_t)(_r * 128 + ((lk8 ^ (_r & 7)) << 4)), \
                      _src + (size_t)(b0 + _r) * HH + _kb + _half * 64 + lk8 * 8); \
        } \
        CP_COMMIT(); \
    } while (0)

    // prefetch preG2 gate vectors for t=0
    float4 pv[2][2];
#pragma unroll
    for (int mi = 0; mi < 2; mi++)
#pragma unroll
        for (int ni = 0; ni < 2; ni++)
            pv[mi][ni] = __ldg((const float4*)(preG2 + ((size_t)bb[mi] * LL + 0) * G4H + hh[ni] * 4));

    for (int t = 0; t < LL; t++) {
        float C[2][2][4];
#pragma unroll
        for (int mi = 0; mi < 2; mi++)
#pragma unroll
            for (int ni = 0; ni < 2; ni++)
#pragma unroll
                for (int e = 0; e < 4; e++) C[mi][ni][e] = 0.f;

        if (t > 0) {
            AISSUE3(0);
            AISSUE3(1);
            AISSUE3(2);
#pragma unroll
            for (int s = 0; s < 4; s++) {
                if (s == 0) { CP_WAIT2(); } else if (s < 3) { CP_WAIT1(); } else { CP_WAIT0(); }
                __syncthreads();
                if (s == 1) AISSUE3(3);
                uint32_t Ab = sb + LSM_A + (s % 3) * 32768;
                const bool dual = (s < 2);
#pragma unroll
                for (int half = 0; half < 4; half++) {
                    uint32_t Abh = Ab + half * 8192;
                    const int kc = (s & 1) * 4 + half;   // compile-time after unroll
#pragma unroll
                    for (int ks = 0; ks < 4; ks++) {
                        uint32_t a[2][4];
#pragma unroll
                        for (int mi = 0; mi < 2; mi++) {
                            int row = wm + mi * 16 + ((lmid & 1) << 3) + lrow8;
                            int k8 = ks * 2 + (lmid >> 1);
                            ldm_x4(a[mi][0], a[mi][1], a[mi][2], a[mi][3],
                                   Abh + row * 128 + ((k8 ^ (row & 7)) << 4));
                        }
#pragma unroll
                        for (int mi = 0; mi < 2; mi++)
#pragma unroll
                            for (int ni = 0; ni < 2; ni++)
                                mma16816(C[mi][ni], a[mi],
                                         Bh[kc][ks][ni * 2], Bh[kc][ks][ni * 2 + 1]);
                        if (dual) {
                            int k8b = kc * 8 + ks * 2 + (lmid & 1);
                            uint32_t boff = (uint32_t)(brow * 1024 +
                                (((k8b & 56) | ((k8b ^ brow) & 7)) << 4));
                            uint32_t bl[4];
                            ldm_x4(bl[0], bl[1], bl[2], bl[3], sb + LSM_BLO + boff);
#pragma unroll
                            for (int mi = 0; mi < 2; mi++)
#pragma unroll
                                for (int ni = 0; ni < 2; ni++)
                                    mma16816(C[mi][ni], a[mi], bl[ni * 2], bl[ni * 2 + 1]);
                        }
                    }
                }
            }
        }

        // epilogue: parity exchange + cell update -> stage in SMEM
#pragma unroll
        for (int mi = 0; mi < 2; mi++) {
#pragma unroll
            for (int ni = 0; ni < 2; ni++) {
                float s0 = parity ? C[mi][ni][0] : C[mi][ni][2];
                float s1 = parity ? C[mi][ni][1] : C[mi][ni][3];
                float r0 = __shfl_xor_sync(0xffffffffu, s0, 1);
                float r1 = __shfl_xor_sync(0xffffffffu, s1, 1);
                float gi, gf, gg, go;
                if (!parity) { gi = C[mi][ni][0]; gf = C[mi][ni][1]; gg = r0; go = r1; }
                else         { gi = r0; gf = r1; gg = C[mi][ni][2]; go = C[mi][ni][3]; }
                gi += pv[mi][ni].x + bgv[ni][0];
                gf += pv[mi][ni].y + bgv[ni][1];
                gg += pv[mi][ni].z + bgv[ni][2];
                go += pv[mi][ni].w + bgv[ni][3];

                float Cn = sigma(gf) * Creg[mi][ni] + sigma(gi) * tanha(gg);
                float hn = sigma(go) * tanha(Cn);
                Creg[mi][ni] = Cn;

                int blc = wm + mi * 16 + qid + parity * 8;
                int hl = (wid >> 1) * 4 + ni * 2 + (tq >> 1);
                stg[blc * 20 + hl] = hn;
                stg[1280 + blc * 20 + hl] = Cn;
                __nv_bfloat16 hb = __float2bfloat16(hn);
                stg16[blc * 16 + hl] = hb;
                stg16[1024 + blc * 16 + hl] = __float2bfloat16(hn - __bfloat162float(hb));
            }
        }
        __syncthreads();

        // coalesced h hi/lo publish (critical path for next step's consumers)
        {
            int i2 = tid & 127;
            int b_l = i2 >> 1, hf = i2 & 1;
            __nv_bfloat16* gdst = (tid < 128) ? g_hhi : g_hlo;
            const __nv_bfloat16* ssrc = stg16 + ((tid < 128) ? 0 : 1024);
            *(uint4*)(gdst + (size_t)(b0 + b_l) * HH + nt * 16 + hf * 8) =
                *(const uint4*)(ssrc + b_l * 16 + hf * 8);
        }

        bool notlast = (t != LL - 1);
        if (notlast) {
            // prefetch next step's preG2, then publish-fence and arrive
#pragma unroll
            for (int mi = 0; mi < 2; mi++)
#pragma unroll
                for (int ni = 0; ni < 2; ni++)
                    pv[mi][ni] = __ldg((const float4*)(preG2 +
                        ((size_t)bb[mi] * LL + (t + 1)) * G4H + hh[ni] * 4));
            __threadfence();
            __syncthreads();
            if (tid == 0) atomicAdd((unsigned*)&g_barg[bt * 64], 1u);
        }

        // coalesced out_h / out_c stores — overlapped with the barrier wait
#pragma unroll
        for (int j = 0; j < 2; j++) {
            int idx = tid * 2 + j;
            int arr = idx >> 8, r = idx & 255;
            int blc = r >> 2, h4 = (r & 3) * 4;
            float4 v = *(const float4*)(stg + arr * 1280 + blc * 20 + h4);
            float* dst = (arr ? out_c : out_h) +
                         ((size_t)(b0 + blc) * LL + t) * HH + nt * 16 + h4;
            __stcs((float4*)dst, v);
        }

        if (notlast) {
            if (tid == 0) {
                unsigned tgt = 32u * (unsigned)(t + 1);
                while (g_barg[bt * 64] < tgt) { __nanosleep(64); }
            }
            __syncthreads();
        }
    }
#undef AISSUE3
}

// ---------------- launch ----------------
extern "C" void kernel_launch(void* const* d_in, const int* in_sizes, int n_in,
                              void* d_out, int out_size) {
    const float* x   = (const float*)d_in[0];
    const float* Wih = (const float*)d_in[1];
    const float* bih = (const float*)d_in[2];
    const float* Wmx = (const float*)d_in[3];
    const float* bmx = (const float*)d_in[4];
    const float* Wmh = (const float*)d_in[5];
    const float* bmh = (const float*)d_in[6];
    const float* Whm = (const float*)d_in[7];
    const float* bhm = (const float*)d_in[8];
    const float* Wa  = (const float*)d_in[9];
    const float* ba  = (const float*)d_in[10];

    float* out    = (float*)d_out;
    float* out_h  = out;
    float* out_c  = out + (size_t)BB * LL * HH;
    float* out_xt = out + (size_t)2 * BB * LL * HH;

    float *preG2, *W2, *Wcomb;
    cudaGetSymbolAddress((void**)&preG2, g_preG2);
    cudaGetSymbolAddress((void**)&W2, g_W2);
    cudaGetSymbolAddress((void**)&Wcomb, g_Wcomb);

    // (1) stacked weight GEMM: [Wmx;Wmh] @ Whm -> {Wcomb(+Wih), W2}
    sgemm_w<<<dim3(G4H / BN, (CC + HH) / BM2), 256>>>(Wmx, Wmh, Whm, Wih, Wcomb, W2);
    // (2) Wcomb -> B2 (interleaved n, split bf16)
    conv_w<<<(G4H * 64) / 256, 256>>>();
    // (3) X -> A2 (split bf16)
    conv_x<<<(BB * LL * CC / 4) / 256, 256>>>(x);
    // (4) preG2 = A2 @ B2^T  (2-buffer proven pipeline)
    cudaFuncSetAttribute(gemm_mma, cudaFuncAttributeMaxDynamicSharedMemorySize, 2 * GSM_BUF);
    gemm_mma<<<dim3(G4H / 128, (BB * LL) / 128), 256, 2 * GSM_BUF>>>(preG2);

    // (5) barrier reset
    zero_init<<<1, 32>>>();
    // (6) attention path
    attn_xtilde<<<BB, 256>>>(x, Wa, ba, out_xt);
    // (7) combined bias row (orig layout)
    bias_comb<<<G4H / 256, 256>>>(bih, bhm, bmx, bmh, Whm);
    // (8) W2 -> W2T hi/lo (tiled transpose, coalesced)
    conv_w2t<<<dim3(16, 64), 256>>>();

    // (9) persistent HMMA recurrence: B-hi register cache + overlapped out stores
    cudaFuncSetAttribute(lstm_mma, cudaFuncAttributeMaxDynamicSharedMemorySize, LSM_TOT);
    lstm_mma<<<dim3(32, 4), 256, LSM_TOT>>>(preG2, out_h, out_c);
}

// round 15
// speedup vs baseline: 1.3676x; 1.0120x over previous
#include <cuda_runtime.h>
#include <cuda_bf16.h>
#include <math.h>
#include <stdint.h>
#include <string.h>

#define BB 256
#define LL 128
#define CC 256
#define HH 512
#define G4H 2048   // 4*HH

// ---------------- scratch (device globals: no allocation allowed) ----------------
__device__ float g_preG2[(size_t)BB * LL * G4H];  // 32768 x 2048, cols interleaved h*4+g
__device__ float g_W2[HH * G4H];                  // Wmh @ Whm (orig col layout)
__device__ float g_Wcomb[CC * G4H];               // Wih + Wmx@Whm (orig col layout)
__device__ float g_biasc[G4H];                    // combined bias row (orig layout)
__device__ volatile unsigned g_barg[256];         // 4 group barrier counters (stride 64)
__device__ alignas(256) __nv_bfloat16 g_A2[(size_t)BB * LL * 768];  // [Xhi|Xhi|Xlo]
__device__ alignas(256) __nv_bfloat16 g_B2[(size_t)G4H * 768];      // [n_il][Whi;Wlo;Whi]
__device__ alignas(256) __nv_bfloat16 g_W2Thi[(size_t)G4H * HH];    // [n_il][k] hi
__device__ alignas(256) __nv_bfloat16 g_W2Tlo[(size_t)G4H * HH];    // [n_il][k] lo
__device__ alignas(256) __nv_bfloat16 g_hhi[BB * HH];               // h bf16 hi [b][k]
__device__ alignas(256) __nv_bfloat16 g_hlo[BB * HH];               // h bf16 lo [b][k]

typedef unsigned long long ull;

// ---------------- helpers ---------------------------------------------------------
__device__ __forceinline__ ull pk2(float x, float y) {
    ull r; asm("mov.b64 %0, {%1, %2};" : "=l"(r) : "f"(x), "f"(y)); return r;
}
__device__ __forceinline__ void upk2(ull v, float& x, float& y) {
    asm("mov.b64 {%0, %1}, %2;" : "=f"(x), "=f"(y) : "l"(v));
}
__device__ __forceinline__ void fma2(ull& d, ull a, ull b) {
    asm("fma.rn.f32x2 %0, %1, %2, %0;" : "+l"(d) : "l"(a), "l"(b));
}
__device__ __forceinline__ float tanha(float x) {
    float y; asm("tanh.approx.f32 %0, %1;" : "=f"(y) : "f"(x)); return y;
}
__device__ __forceinline__ float sigma(float x) {
    return fmaf(tanha(x * 0.5f), 0.5f, 0.5f);
}
__device__ __forceinline__ uint32_t smem_u32(const void* p) {
    uint32_t a;
    asm("{ .reg .u64 t; cvta.to.shared.u64 t, %1; cvt.u32.u64 %0, t; }" : "=r"(a) : "l"(p));
    return a;
}
__device__ __forceinline__ void ldm_x4(uint32_t& r0, uint32_t& r1, uint32_t& r2,
                                       uint32_t& r3, uint32_t addr) {
    asm volatile("ldmatrix.sync.aligned.m8n8.x4.shared.b16 {%0,%1,%2,%3}, [%4];"
                 : "=r"(r0), "=r"(r1), "=r"(r2), "=r"(r3) : "r"(addr));
}
__device__ __forceinline__ void mma16816(float* d, const uint32_t* a, uint32_t b0, uint32_t b1) {
    asm volatile("mma.sync.aligned.m16n8k16.row.col.f32.bf16.bf16.f32 "
                 "{%0,%1,%2,%3}, {%4,%5,%6,%7}, {%8,%9}, {%0,%1,%2,%3};"
                 : "+f"(d[0]), "+f"(d[1]), "+f"(d[2]), "+f"(d[3])
                 : "r"(a[0]), "r"(a[1]), "r"(a[2]), "r"(a[3]), "r"(b0), "r"(b1));
}
__device__ __forceinline__ void cpasync16(uint32_t dst, const void* src) {
    asm volatile("cp.async.cg.shared.global [%0], [%1], 16;" :: "r"(dst), "l"(src) : "memory");
}
#define CP_COMMIT() asm volatile("cp.async.commit_group;" ::: "memory")
#define CP_WAIT3()  asm volatile("cp.async.wait_group 3;" ::: "memory")
#define CP_WAIT2()  asm volatile("cp.async.wait_group 2;" ::: "memory")
#define CP_WAIT1()  asm volatile("cp.async.wait_group 1;" ::: "memory")
#define CP_WAIT0()  asm volatile("cp.async.wait_group 0;" ::: "memory")

// ---------------- init ------------------------------------------------------------
__global__ void zero_init() {
    int i = threadIdx.x;
    if (i < 4) g_barg[i * 64] = 0u;
}

// ---------------- attention: softmax is time-invariant ---------------------------
__global__ void attn_xtilde(const float* __restrict__ x, const float* __restrict__ Wa,
                            const float* __restrict__ ba, float* __restrict__ out_xt) {
    int b = blockIdx.x;
    int c = threadIdx.x;
    __shared__ float wx[LL];
    __shared__ float red[CC];
    if (c < LL) wx[c] = Wa[2 * HH + c];
    __syncthreads();

    const float* xb = x + (size_t)b * LL * CC;
    float s = 0.f;
#pragma unroll 4
    for (int l = 0; l < LL; l++) s += xb[l * CC + c] * wx[l];
    s += ba[0];

    red[c] = s; __syncthreads();
#pragma unroll
    for (int st = 128; st > 0; st >>= 1) {
        if (c < st) red[c] = fmaxf(red[c], red[c + st]);
        __syncthreads();
    }
    float m = red[0];
    __syncthreads();
    float e = expf(s - m);
    red[c] = e; __syncthreads();
#pragma unroll
    for (int st = 128; st > 0; st >>= 1) {
        if (c < st) red[c] += red[c + st];
        __syncthreads();
    }
    float alpha = e / red[0];

    float* ob = out_xt + (size_t)b * LL * CC;
#pragma unroll 4
    for (int l = 0; l < LL; l++) ob[l * CC + c] = alpha * xb[l * CC + c];
}

// ---------------- combined bias row: bih + bhm + (bmx+bmh)@Whm --------------------
__global__ void bias_comb(const float* __restrict__ bih, const float* __restrict__ bhm,
                          const float* __restrict__ bmx, const float* __restrict__ bmh,
                          const float* __restrict__ Whm) {
    __shared__ float bm[HH];
    int tid = threadIdx.x;
    for (int i = tid; i < HH; i += 256) bm[i] = bmx[i] + bmh[i];
    __syncthreads();
    int j = blockIdx.x * 256 + tid;
    float s = bih[j] + bhm[j];
#pragma unroll 8
    for (int k = 0; k < HH; k++) s += bm[k] * Whm[(size_t)k * G4H + j];
    g_biasc[j] = s;
}

// ---------------- stacked weight SGEMM: [Wmx;Wmh] @ Whm -> {Wcomb, W2} -----------
#define BM2 64
#define BN 128
#define BK 16

__global__ __launch_bounds__(256, 2) void sgemm_w(
    const float* __restrict__ Wmx, const float* __restrict__ Wmh,
    const float* __restrict__ Whm, const float* __restrict__ Wih,
    float* __restrict__ Wcomb, float* __restrict__ W2) {
    __shared__ alignas(16) float As[BK][BM2 + 4];
    __shared__ alignas(16) float Bs[BK][BN];

    int tid = threadIdx.x;
    int bm = blockIdx.y * BM2;
    int bn = blockIdx.x * BN;
    int tx = tid & 15, ty = tid >> 4;
    int row = ty * 4, col = tx * 8;

    const int lr = tid >> 2;
    const int lq = (tid & 3) << 2;
    int r_glob = bm + lr;
    const float* Asrc = (r_glob < CC) ? (Wmx + (size_t)r_glob * HH)
                                      : (Wmh + (size_t)(r_glob - CC) * HH);

    ull acc[4][4];
#pragma unroll
    for (int i = 0; i < 4; i++)
#pragma unroll
        for (int j = 0; j < 4; j++) acc[i][j] = 0ULL;

    for (int k0 = 0; k0 < HH; k0 += BK) {
        {
            float4 v = *(const float4*)(Asrc + k0 + lq);
            As[lq + 0][lr] = v.x; As[lq + 1][lr] = v.y;
            As[lq + 2][lr] = v.z; As[lq + 3][lr] = v.w;
        }
#pragma unroll
        for (int i = 0; i < 2; i++) {
            int idx = tid + i * 256;
            int r = idx >> 5;
            int c = (idx & 31) << 2;
            *(float4*)&Bs[r][c] = *(const float4*)(Whm + (size_t)(k0 + r) * G4H + bn + c);
        }
        __syncthreads();
#pragma unroll
        for (int kk = 0; kk < BK; kk++) {
            float4 a0 = *(const float4*)&As[kk][row];
            float4 b0 = *(const float4*)&Bs[kk][col];
            float4 b1 = *(const float4*)&Bs[kk][col + 4];
            ull bp0 = pk2(b0.x, b0.y), bp1 = pk2(b0.z, b0.w);
            ull bp2 = pk2(b1.x, b1.y), bp3 = pk2(b1.z, b1.w);
            float av[4] = {a0.x, a0.y, a0.z, a0.w};
#pragma unroll
            for (int i = 0; i < 4; i++) {
                ull ap = pk2(av[i], av[i]);
                fma2(acc[i][0], ap, bp0);
                fma2(acc[i][1], ap, bp1);
                fma2(acc[i][2], ap, bp2);
                fma2(acc[i][3], ap, bp3);
            }
        }
        __syncthreads();
    }

#pragma unroll
    for (int i = 0; i < 4; i++) {
        int rg = bm + row + i;
        float o[8];
#pragma unroll
        for (int j = 0; j < 4; j++) upk2(acc[i][j], o[2 * j], o[2 * j + 1]);
        float* outp;
        if (rg < CC) {
            size_t off = (size_t)rg * G4H + bn + col;
            float4 c0 = *(const float4*)(Wih + off);
            float4 c1 = *(const float4*)(Wih + off + 4);
            o[0] += c0.x; o[1] += c0.y; o[2] += c0.z; o[3] += c0.w;
            o[4] += c1.x; o[5] += c1.y; o[6] += c1.z; o[7] += c1.w;
            outp = Wcomb + off;
        } else {
            outp = W2 + (size_t)(rg - CC) * G4H + bn + col;
        }
        *(float4*)(outp) = make_float4(o[0], o[1], o[2], o[3]);
        *(float4*)(outp + 4) = make_float4(o[4], o[5], o[6], o[7]);
    }
}

// ---------------- bf16 split conversions ------------------------------------------
__device__ __forceinline__ uint32_t pkbf2(float a, float b) {
    __nv_bfloat162 h2 = __floats2bfloat162_rn(a, b);
    return *(uint32_t*)&h2;
}

// x [32768 x 256] fp32 -> A2 [32768 x 768] bf16 (cols: [hi | hi | lo])
__global__ void conv_x(const float* __restrict__ x) {
    int i = blockIdx.x * blockDim.x + threadIdx.x;
    int m = i >> 6;
    int c = (i & 63) << 2;
    float4 v = *(const float4*)(x + (size_t)m * CC + c);
    float h0 = __bfloat162float(__float2bfloat16(v.x));
    float h1 = __bfloat162float(__float2bfloat16(v.y));
    float h2 = __bfloat162float(__float2bfloat16(v.z));
    float h3 = __bfloat162float(__float2bfloat16(v.w));
    uint2 hi = make_uint2(pkbf2(v.x, v.y), pkbf2(v.z, v.w));
    uint2 lo = make_uint2(pkbf2(v.x - h0, v.y - h1), pkbf2(v.z - h2, v.w - h3));
    __nv_bfloat16* row = g_A2 + (size_t)m * 768;
    *(uint2*)(row + c) = hi;
    *(uint2*)(row + 256 + c) = hi;
    *(uint2*)(row + 512 + c) = lo;
}

// Wcomb [256 k x 2048 c orig] -> B2 [2048 n x 768] bf16 (k: [hi | lo | hi])
// tiled: coalesced float4 reads, 8B row-chunk writes. n = (c&511)*4 + (c>>9).
__global__ void conv_w() {
    __shared__ __nv_bfloat16 shi[32][36];
    __shared__ __nv_bfloat16 slo[32][36];
    int k0 = blockIdx.x * 32;     // 8 blocks
    int c0 = blockIdx.y * 32;     // 64 blocks
    int tid = threadIdx.x;

    {
        int r = tid >> 3;
        int c4 = (tid & 7) * 4;
        float4 v = *(const float4*)&g_Wcomb[(size_t)(k0 + r) * G4H + c0 + c4];
        float h0 = __bfloat162float(__float2bfloat16(v.x));
        float h1 = __bfloat162float(__float2bfloat16(v.y));
        float h2 = __bfloat162float(__float2bfloat16(v.z));
        float h3 = __bfloat162float(__float2bfloat16(v.w));
        shi[r][c4 + 0] = __float2bfloat16(v.x);
        shi[r][c4 + 1] = __float2bfloat16(v.y);
        shi[r][c4 + 2] = __float2bfloat16(v.z);
        shi[r][c4 + 3] = __float2bfloat16(v.w);
        slo[r][c4 + 0] = __float2bfloat16(v.x - h0);
        slo[r][c4 + 1] = __float2bfloat16(v.y - h1);
        slo[r][c4 + 2] = __float2bfloat16(v.z - h2);
        slo[r][c4 + 3] = __float2bfloat16(v.w - h3);
    }
    __syncthreads();
    {
        int c = tid >> 3;
        int r4 = (tid & 7) * 4;
        int cg = c0 + c;
        int n = (cg & 511) * 4 + (cg >> 9);
        uint2 uh, ul;
        __nv_bfloat16* ph = (__nv_bfloat16*)&uh;
        __nv_bfloat16* pl = (__nv_bfloat16*)&ul;
#pragma unroll
        for (int i = 0; i < 4; i++) { ph[i] = shi[r4 + i][c]; pl[i] = slo[r4 + i][c]; }
        __nv_bfloat16* row = g_B2 + (size_t)n * 768;
        *(uint2*)(row + k0 + r4) = uh;
        *(uint2*)(row + 256 + k0 + r4) = ul;
        *(uint2*)(row + 512 + k0 + r4) = uh;
    }
}

// W2 [512 k x 2048 orig] -> W2T hi/lo [2048 interleaved-n x 512 k] bf16
__global__ void conv_w2t() {
    __shared__ __nv_bfloat16 shi[32][34];
    __shared__ __nv_bfloat16 slo[32][34];
    int k0 = blockIdx.x * 32;
    int c0 = blockIdx.y * 32;
    int tid = threadIdx.x;

    {
        int r = tid >> 3;
        int c4 = (tid & 7) * 4;
        float4 v = *(const float4*)&g_W2[(size_t)(k0 + r) * G4H + c0 + c4];
        float h0 = __bfloat162float(__float2bfloat16(v.x));
        float h1 = __bfloat162float(__float2bfloat16(v.y));
        float h2 = __bfloat162float(__float2bfloat16(v.z));
        float h3 = __bfloat162float(__float2bfloat16(v.w));
        shi[r][c4 + 0] = __float2bfloat16(v.x);
        shi[r][c4 + 1] = __float2bfloat16(v.y);
        shi[r][c4 + 2] = __float2bfloat16(v.z);
        shi[r][c4 + 3] = __float2bfloat16(v.w);
        slo[r][c4 + 0] = __float2bfloat16(v.x - h0);
        slo[r][c4 + 1] = __float2bfloat16(v.y - h1);
        slo[r][c4 + 2] = __float2bfloat16(v.z - h2);
        slo[r][c4 + 3] = __float2bfloat16(v.w - h3);
    }
    __syncthreads();
    {
        int c = tid >> 3;
        int r4 = (tid & 7) * 4;
        int cg = c0 + c;
        int n = (cg & 511) * 4 + (cg >> 9);
        uint2 uh, ul;
        __nv_bfloat16* ph = (__nv_bfloat16*)&uh;
        __nv_bfloat16* pl = (__nv_bfloat16*)&ul;
#pragma unroll
        for (int i = 0; i < 4; i++) { ph[i] = shi[r4 + i][c]; pl[i] = slo[r4 + i][c]; }
        *(uint2*)&g_W2Thi[(size_t)n * HH + k0 + r4] = uh;
        *(uint2*)&g_W2Tlo[(size_t)n * HH + k0 + r4] = ul;
    }
}

// ---------------- HMMA GEMM: preG2 = A2 @ B2^T (proven 2-buffer) -----------------
#define GSM_BUF 32768   // A 16KB + B 16KB per buffer

__global__ __launch_bounds__(256) void gemm_mma(float* __restrict__ Cm) {
    extern __shared__ char sm[];
    uint32_t sb = smem_u32(sm);
    const int tid = threadIdx.x;
    const int wid = tid >> 5, lane = tid & 31;
    const int bn = blockIdx.x * 128, bm = blockIdx.y * 128;
    const int wm0 = (wid & 1) * 64, wn0 = (wid >> 1) * 32;

    float C[4][4][4];
#pragma unroll
    for (int mi = 0; mi < 4; mi++)
#pragma unroll
        for (int ni = 0; ni < 4; ni++)
#pragma unroll
            for (int e = 0; e < 4; e++) C[mi][ni][e] = 0.f;

    const int lr = tid >> 3;
    const int lk8 = tid & 7;
#define ISSUE(kc) do { \
        int _buf = (kc) & 1; \
        uint32_t _Ab = sb + _buf * GSM_BUF; \
        uint32_t _Bb = _Ab + 16384; \
        _Pragma("unroll") \
        for (int _it = 0; _it < 4; _it++) { \
            int _r = lr + _it * 32; \
            uint32_t _sw = (uint32_t)(_r * 128 + ((lk8 ^ (_r & 7)) << 4)); \
            cpasync16(_Ab + _sw, g_A2 + (size_t)(bm + _r) * 768 + (kc) * 64 + lk8 * 8); \
            cpasync16(_Bb + _sw, g_B2 + (size_t)(bn + _r) * 768 + (kc) * 64 + lk8 * 8); \
        } \
        CP_COMMIT(); \
    } while (0)

    ISSUE(0);
    ISSUE(1);

    const int lmid = lane >> 3;
    const int lrow8 = lane & 7;

    for (int kc = 0; kc < 12; kc++) {
        int buf = kc & 1;
        if (kc < 11) { CP_WAIT1(); } else { CP_WAIT0(); }
        __syncthreads();
        uint32_t Ab = sb + buf * GSM_BUF;
        uint32_t Bb = Ab + 16384;
#pragma unroll
        for (int ks = 0; ks < 4; ks++) {
            uint32_t a[4][4], b[2][4];
#pragma unroll
            for (int mi = 0; mi < 4; mi++) {
                int row = wm0 + mi * 16 + ((lmid & 1) << 3) + lrow8;
                int k8 = ks * 2 + (lmid >> 1);
                ldm_x4(a[mi][0], a[mi][1], a[mi][2], a[mi][3],
                       Ab + row * 128 + ((k8 ^ (row & 7)) << 4));
            }
#pragma unroll
            for (int nb = 0; nb < 2; nb++) {
                int row = wn0 + nb * 16 + ((lmid >> 1) << 3) + lrow8;
                int k8 = ks * 2 + (lmid & 1);
                ldm_x4(b[nb][0], b[nb][1], b[nb][2], b[nb][3],
                       Bb + row * 128 + ((k8 ^ (row & 7)) << 4));
            }
#pragma unroll
            for (int mi = 0; mi < 4; mi++)
#pragma unroll
                for (int ni = 0; ni < 4; ni++)
                    mma16816(C[mi][ni], a[mi],
                             b[ni >> 1][(ni & 1) * 2], b[ni >> 1][(ni & 1) * 2 + 1]);
        }
        __syncthreads();
        if (kc + 2 < 12) ISSUE(kc + 2);
    }

    const int qid = lane >> 2, tq = lane & 3;
#pragma unroll
    for (int ni = 0; ni < 4; ni++) {
        int col = bn + wn0 + ni * 8 + tq * 2;
#pragma unroll
        for (int mi = 0; mi < 4; mi++) {
            int row = bm + wm0 + mi * 16 + qid;
            *(float2*)(Cm + (size_t)row * G4H + col) = make_float2(C[mi][ni][0], C[mi][ni][1]);
            *(float2*)(Cm + (size_t)(row + 8) * G4H + col) = make_float2(C[mi][ni][2], C[mi][ni][3]);
        }
    }
#undef ISSUE
}

// ---------------- HMMA persistent recurrence (4th buffer in dead W-hi SMEM) -------
// 128 CTAs: x = n-tile, y = b-tile. B-hi frags cached in regs (W-hi SMEM dead after
// preload -> reused as slot-3 buffer). All 4 slots issued right after the barrier.
#define LSM_BLO 65536
#define LSM_A   131072
#define LSM_TOT (131072 + 3 * 32768)   // 229376 bytes

__global__ __launch_bounds__(256, 1) void lstm_mma(
    const float* __restrict__ preG2, float* __restrict__ out_h, float* __restrict__ out_c) {
    extern __shared__ char sm[];
    uint32_t sb = smem_u32(sm);
    const int tid = threadIdx.x;
    const int wid = tid >> 5, lane = tid & 31;
    const int nt = blockIdx.x, bt = blockIdx.y;
    const int b0 = bt * 64;
    const int n0 = nt * 64;
    const int wm = (wid & 1) * 32, wn = (wid >> 1) * 16;
    const int lmid = lane >> 3, lrow8 = lane & 7;
    const int qid = lane >> 2, tq = lane & 3;
    const int parity = tq & 1;
    const int lr = tid >> 3, lk8 = tid & 7;

    float* stg = (float*)(sm + LSM_A + 2 * 32768);
    __nv_bfloat16* stg16 = (__nv_bfloat16*)(sm + LSM_A + 2 * 32768 + 10240);

    // load W2T slices (hi/lo) into SMEM once: 64 n-rows x 512 k, swizzled
    for (int i = tid; i < 4096; i += 256) {
        int r = i >> 6, c = i & 63;
        uint32_t dst = (uint32_t)(r * 1024 + (((c & 56) | ((c ^ r) & 7)) << 4));
        *(uint4*)(sm + dst) = *(const uint4*)(g_W2Thi + (size_t)(n0 + r) * HH + c * 8);
        *(uint4*)(sm + LSM_BLO + dst) = *(const uint4*)(g_W2Tlo + (size_t)(n0 + r) * HH + c * 8);
    }

    int bb[2], hh[2];
#pragma unroll
    for (int mi = 0; mi < 2; mi++) bb[mi] = b0 + wm + mi * 16 + qid + parity * 8;
#pragma unroll
    for (int ni = 0; ni < 2; ni++) hh[ni] = nt * 16 + (wid >> 1) * 4 + ni * 2 + (tq >> 1);

    float bgv[2][4];
#pragma unroll
    for (int ni = 0; ni < 2; ni++)
#pragma unroll
        for (int g = 0; g < 4; g++) bgv[ni][g] = g_biasc[g * HH + hh[ni]];

    float Creg[2][2] = {{0.f, 0.f}, {0.f, 0.f}};
    __syncthreads();

    // ---- preload ALL B-hi fragments into registers (step-invariant); W-hi region
    //      becomes dead afterwards and is reused as slot-3's A buffer. ----
    const int brow = wn + ((lmid >> 1) << 3) + lrow8;
    uint32_t Bh[8][4][4];
#pragma unroll
    for (int kc = 0; kc < 8; kc++)
#pragma unroll
        for (int ks = 0; ks < 4; ks++) {
            int k8b = kc * 8 + ks * 2 + (lmid & 1);
            uint32_t boff = (uint32_t)(brow * 1024 + (((k8b & 56) | ((k8b ^ brow) & 7)) << 4));
            ldm_x4(Bh[kc][ks][0], Bh[kc][ks][1], Bh[kc][ks][2], Bh[kc][ks][3], sb + boff);
        }
    __syncthreads();   // all W-hi reads done before region reuse

#define ABUF(s) (((s) == 3) ? sb : (sb + LSM_A + (s) * 32768))
#define AISSUE4(s) do { \
        uint32_t _ab = ABUF(s); \
        const __nv_bfloat16* _src = ((s) < 2) ? g_hhi : g_hlo; \
        int _kb = ((s) & 1) * 256; \
        _Pragma("unroll") \
        for (int _it = 0; _it < 8; _it++) { \
            int _half = _it >> 1; \
            int _r = lr + (_it & 1) * 32; \
            cpasync16(_ab + _half * 8192 + (uint32_t)(_r * 128 + ((lk8 ^ (_r & 7)) << 4)), \
                      _src + (size_t)(b0 + _r) * HH + _kb + _half * 64 + lk8 * 8); \
        } \
        CP_COMMIT(); \
    } while (0)

    // prefetch preG2 gate vectors for t=0
    float4 pv[2][2];
#pragma unroll
    for (int mi = 0; mi < 2; mi++)
#pragma unroll
        for (int ni = 0; ni < 2; ni++)
            pv[mi][ni] = __ldg((const float4*)(preG2 + ((size_t)bb[mi] * LL + 0) * G4H + hh[ni] * 4));

    for (int t = 0; t < LL; t++) {
        float C[2][2][4];
#pragma unroll
        for (int mi = 0; mi < 2; mi++)
#pragma unroll
            for (int ni = 0; ni < 2; ni++)
#pragma unroll
                for (int e = 0; e < 4; e++) C[mi][ni][e] = 0.f;

        if (t > 0) {
            AISSUE4(0);
            AISSUE4(1);
            AISSUE4(2);
            AISSUE4(3);
#pragma unroll
            for (int s = 0; s < 4; s++) {
                if (s == 0) { CP_WAIT3(); } else if (s == 1) { CP_WAIT2(); }
                else if (s == 2) { CP_WAIT1(); } else { CP_WAIT0(); }
                __syncthreads();
                uint32_t Ab = ABUF(s);
                const bool dual = (s < 2);
#pragma unroll
                for (int half = 0; half < 4; half++) {
                    uint32_t Abh = Ab + half * 8192;
                    const int kc = (s & 1) * 4 + half;
#pragma unroll
                    for (int ks = 0; ks < 4; ks++) {
                        uint32_t a[2][4];
#pragma unroll
                        for (int mi = 0; mi < 2; mi++) {
                            int row = wm + mi * 16 + ((lmid & 1) << 3) + lrow8;
                            int k8 = ks * 2 + (lmid >> 1);
                            ldm_x4(a[mi][0], a[mi][1], a[mi][2], a[mi][3],
                                   Abh + row * 128 + ((k8 ^ (row & 7)) << 4));
                        }
#pragma unroll
                        for (int mi = 0; mi < 2; mi++)
#pragma unroll
                            for (int ni = 0; ni < 2; ni++)
                                mma16816(C[mi][ni], a[mi],
                                         Bh[kc][ks][ni * 2], Bh[kc][ks][ni * 2 + 1]);
                        if (dual) {
                            int k8b = kc * 8 + ks * 2 + (lmid & 1);
                            uint32_t boff = (uint32_t)(brow * 1024 +
                                (((k8b & 56) | ((k8b ^ brow) & 7)) << 4));
                            uint32_t bl[4];
                            ldm_x4(bl[0], bl[1], bl[2], bl[3], sb + LSM_BLO + boff);
#pragma unroll
                            for (int mi = 0; mi < 2; mi++)
#pragma unroll
                                for (int ni = 0; ni < 2; ni++)
                                    mma16816(C[mi][ni], a[mi], bl[ni * 2], bl[ni * 2 + 1]);
                        }
                    }
                }
            }
        }

        // epilogue: parity exchange + cell update -> stage in SMEM
#pragma unroll
        for (int mi = 0; mi < 2; mi++) {
#pragma unroll
            for (int ni = 0; ni < 2; ni++) {
                float s0 = parity ? C[mi][ni][0] : C[mi][ni][2];
                float s1 = parity ? C[mi][ni][1] : C[mi][ni][3];
                float r0 = __shfl_xor_sync(0xffffffffu, s0, 1);
                float r1 = __shfl_xor_sync(0xffffffffu, s1, 1);
                float gi, gf, gg, go;
                if (!parity) { gi = C[mi][ni][0]; gf = C[mi][ni][1]; gg = r0; go = r1; }
                else         { gi = r0; gf = r1; gg = C[mi][ni][2]; go = C[mi][ni][3]; }
                gi += pv[mi][ni].x + bgv[ni][0];
                gf += pv[mi][ni].y + bgv[ni][1];
                gg += pv[mi][ni].z + bgv[ni][2];
                go += pv[mi][ni].w + bgv[ni][3];

                float Cn = sigma(gf) * Creg[mi][ni] + sigma(gi) * tanha(gg);
                float hn = sigma(go) * tanha(Cn);
                Creg[mi][ni] = Cn;

                int blc = wm + mi * 16 + qid + parity * 8;
                int hl = (wid >> 1) * 4 + ni * 2 + (tq >> 1);
                stg[blc * 20 + hl] = hn;
                stg[1280 + blc * 20 + hl] = Cn;
                __nv_bfloat16 hb = __float2bfloat16(hn);
                stg16[blc * 16 + hl] = hb;
                stg16[1024 + blc * 16 + hl] = __float2bfloat16(hn - __bfloat162float(hb));
            }
        }
        __syncthreads();

        // coalesced h hi/lo publish (critical path for next step's consumers)
        {
            int i2 = tid & 127;
            int b_l = i2 >> 1, hf = i2 & 1;
            __nv_bfloat16* gdst = (tid < 128) ? g_hhi : g_hlo;
            const __nv_bfloat16* ssrc = stg16 + ((tid < 128) ? 0 : 1024);
            *(uint4*)(gdst + (size_t)(b0 + b_l) * HH + nt * 16 + hf * 8) =
                *(const uint4*)(ssrc + b_l * 16 + hf * 8);
        }

        bool notlast = (t != LL - 1);
        if (notlast) {
#pragma unroll
            for (int mi = 0; mi < 2; mi++)
#pragma unroll
                for (int ni = 0; ni < 2; ni++)
                    pv[mi][ni] = __ldg((const float4*)(preG2 +
                        ((size_t)bb[mi] * LL + (t + 1)) * G4H + hh[ni] * 4));
            __threadfence();
            __syncthreads();
            if (tid == 0) atomicAdd((unsigned*)&g_barg[bt * 64], 1u);
        }

        // coalesced out_h / out_c stores — overlapped with the barrier wait
#pragma unroll
        for (int j = 0; j < 2; j++) {
            int idx = tid * 2 + j;
            int arr = idx >> 8, r = idx & 255;
            int blc = r >> 2, h4 = (r & 3) * 4;
            float4 v = *(const float4*)(stg + arr * 1280 + blc * 20 + h4);
            float* dst = (arr ? out_c : out_h) +
                         ((size_t)(b0 + blc) * LL + t) * HH + nt * 16 + h4;
            __stcs((float4*)dst, v);
        }

        if (notlast) {
            if (tid == 0) {
                unsigned tgt = 32u * (unsigned)(t + 1);
                while (g_barg[bt * 64] < tgt) { __nanosleep(64); }
            }
            __syncthreads();
        }
    }
#undef AISSUE4
#undef ABUF
}

// ---------------- launch ----------------
extern "C" void kernel_launch(void* const* d_in, const int* in_sizes, int n_in,
                              void* d_out, int out_size) {
    const float* x   = (const float*)d_in[0];
    const float* Wih = (const float*)d_in[1];
    const float* bih = (const float*)d_in[2];
    const float* Wmx = (const float*)d_in[3];
    const float* bmx = (const float*)d_in[4];
    const float* Wmh = (const float*)d_in[5];
    const float* bmh = (const float*)d_in[6];
    const float* Whm = (const float*)d_in[7];
    const float* bhm = (const float*)d_in[8];
    const float* Wa  = (const float*)d_in[9];
    const float* ba  = (const float*)d_in[10];

    float* out    = (float*)d_out;
    float* out_h  = out;
    float* out_c  = out + (size_t)BB * LL * HH;
    float* out_xt = out + (size_t)2 * BB * LL * HH;

    float *preG2, *W2, *Wcomb;
    cudaGetSymbolAddress((void**)&preG2, g_preG2);
    cudaGetSymbolAddress((void**)&W2, g_W2);
    cudaGetSymbolAddress((void**)&Wcomb, g_Wcomb);

    // (1) stacked weight GEMM: [Wmx;Wmh] @ Whm -> {Wcomb(+Wih), W2}
    sgemm_w<<<dim3(G4H / BN, (CC + HH) / BM2), 256>>>(Wmx, Wmh, Whm, Wih, Wcomb, W2);
    // (2) Wcomb -> B2 (tiled transpose, coalesced)
    conv_w<<<dim3(8, 64), 256>>>();
    // (3) X -> A2 (split bf16)
    conv_x<<<(BB * LL * CC / 4) / 256, 256>>>(x);
    // (4) preG2 = A2 @ B2^T  (2-buffer proven pipeline)
    cudaFuncSetAttribute(gemm_mma, cudaFuncAttributeMaxDynamicSharedMemorySize, 2 * GSM_BUF);
    gemm_mma<<<dim3(G4H / 128, (BB * LL) / 128), 256, 2 * GSM_BUF>>>(preG2);

    // (5) barrier reset
    zero_init<<<1, 32>>>();
    // (6) attention path
    attn_xtilde<<<BB, 256>>>(x, Wa, ba, out_xt);
    // (7) combined bias row (orig layout)
    bias_comb<<<G4H / 256, 256>>>(bih, bhm, bmx, bmh, Whm);
    // (8) W2 -> W2T hi/lo (tiled transpose, coalesced)
    conv_w2t<<<dim3(16, 64), 256>>>();

    // (9) persistent HMMA recurrence: 4-buffer (slot 3 in dead W-hi region)
    cudaFuncSetAttribute(lstm_mma, cudaFuncAttributeMaxDynamicSharedMemorySize, LSM_TOT);
    lstm_mma<<<dim3(32, 4), 256, LSM_TOT>>>(preG2, out_h, out_c);
}